// round 12
// baseline (speedup 1.0000x reference)
#include <cuda_runtime.h>
#include <cuda_fp16.h>

#define LEAK  0.1f
#define BNEPS 1e-5f

#define NB    64
#define HW    361            // 19*19
#define H19   19
#define C2IN  1280
#define C2K   11520          // 1280*9 (fp16 K total)
#define KWORD 5760           // C2K/2 u32 words per weight row
#define KO    600
#define KOP   640
#define NPIX  (NB * HW)      // 23104

#define SROW  20             // smem row stride in u32 (80 B)
#define AH0w  0              // A k-words 0..15 of iter
#define AH1w  2560           // A k-words 16..31
#define BH0w  5120
#define BH1w  7680
#define STG   10240          // u32 per stage
#define SMEMB (2 * STG * 4)  // 81920 bytes

// ---------------- device scratch ----------------
__device__ float g_w1t[512 * 64];
__device__ float g_s1[64],  g_h1[64];
__device__ float g_s2[1024], g_h2[1024];
__device__ float g_cb[KO];
__device__ unsigned g_xh2[(size_t)(C2IN / 2) * NPIX];  // conv2 input, ch-paired fp16 [c/2][gpix]
__device__ unsigned g_ps2[(size_t)512 * NPIX];         // det input, ch-paired fp16 [c/2][gpix]
__device__ __align__(16) unsigned g_w2s[(size_t)1024 * KWORD]; // w2 fp16 pairs, K-order r*1280+c
__device__ __align__(16) unsigned g_rws[(size_t)KOP * 512];    // reweight fp16 pairs

__device__ __forceinline__ unsigned pack2(float lo, float hi)
{
    __half2 h = __floats2half2_rn(lo, hi);
    return *reinterpret_cast<unsigned*>(&h);
}

// ---------------- cp.async helpers ----------------
__device__ __forceinline__ void cp16(void* smem, const void* g)
{
    unsigned sa = (unsigned)__cvta_generic_to_shared(smem);
    asm volatile("cp.async.cg.shared.global [%0], [%1], 16;\n" :: "r"(sa), "l"(g));
}
__device__ __forceinline__ void cp_commit() { asm volatile("cp.async.commit_group;\n"); }
__device__ __forceinline__ void cp_wait0()  { asm volatile("cp.async.wait_group 0;\n"); }

// ---------------- prep ----------------
__global__ void prep_kernel(const float* __restrict__ w1,
                            const float* __restrict__ g1, const float* __restrict__ b1,
                            const float* __restrict__ m1, const float* __restrict__ v1,
                            const float* __restrict__ g2, const float* __restrict__ b2,
                            const float* __restrict__ m2, const float* __restrict__ v2,
                            const float* __restrict__ rw, const float* __restrict__ w2)
{
    long long i = (long long)blockIdx.x * blockDim.x + threadIdx.x;
    if (i < (long long)1024 * KWORD) {
        int co = (int)(i / KWORD);
        int j  = (int)(i - (long long)co * KWORD);
        int r  = j / 640;
        int c  = (j - r * 640) * 2;
        float x0 = w2[(size_t)co * C2K + c * 9 + r];
        float x1 = w2[(size_t)co * C2K + (c + 1) * 9 + r];
        g_w2s[i] = pack2(x0, x1);
    }
    if (i < (long long)KOP * 512) {
        int m = (int)(i >> 9), j = (int)(i & 511);
        float x0 = (m < KO) ? rw[m * 1025 + 2 * j]     : 0.f;
        float x1 = (m < KO) ? rw[m * 1025 + 2 * j + 1] : 0.f;
        g_rws[i] = pack2(x0, x1);
    }
    if (i < 512 * 64) {
        int k = (int)(i >> 6), co = (int)(i & 63);
        g_w1t[i] = w1[co * 512 + k];
    }
    if (i < KO)   g_cb[i] = rw[i * 1025 + 1024];
    if (i < 64)   { float s = g1[i] * rsqrtf(v1[i] + BNEPS); g_s1[i] = s; g_h1[i] = b1[i] - m1[i] * s; }
    if (i < 1024) { float s = g2[i] * rsqrtf(v2[i] + BNEPS); g_s2[i] = s; g_h2[i] = b2[i] - m2[i] * s; }
}

// ---------------- feat0 -> g_xh2 channel-pairs 128..639 ----------------
__global__ void feat0_split(const float* __restrict__ feat0)
{
    long long i = (long long)blockIdx.x * blockDim.x + threadIdx.x;
    if (i < (long long)NB * 512 * HW) {
        int hw = (int)(i % HW);
        long long t = i / HW;
        int cp = (int)(t & 511);
        int b  = (int)(t >> 9);
        const float* src = feat0 + ((size_t)b * 1024 + 2 * cp) * HW + hw;
        g_xh2[(size_t)(128 + cp) * NPIX + b * HW + hw] = pack2(src[0], src[HW]);
    }
}

// ---------------- conv1 (1x1, 512->64) + BN + leaky + reorg(2) --------------
__global__ __launch_bounds__(256) void conv1_kernel(const float* __restrict__ feat1)
{
    __shared__ __align__(16) float s_in[512][16];
    __shared__ float s_w[64][64];

    const int b    = blockIdx.y;
    const int base = blockIdx.x * 16;
    const float* f = feat1 + (size_t)b * 512 * 1444;

    for (int idx = threadIdx.x; idx < 512 * 16; idx += 256) {
        int p = idx & 15, k = idx >> 4;
        int pix = base + p;
        s_in[k][p] = (pix < 1444) ? f[k * 1444 + pix] : 0.f;
    }

    const int co = threadIdx.x & 63;
    const int pq = threadIdx.x >> 6;
    float acc[4] = {0.f, 0.f, 0.f, 0.f};

    for (int kc = 0; kc < 512; kc += 64) {
        __syncthreads();
        for (int idx = threadIdx.x; idx < 64 * 64; idx += 256)
            s_w[idx >> 6][idx & 63] = g_w1t[(kc + (idx >> 6)) * 64 + (idx & 63)];
        __syncthreads();
        #pragma unroll
        for (int kk = 0; kk < 64; kk++) {
            float  w = s_w[kk][co];
            float4 v = *(const float4*)&s_in[kc + kk][pq * 4];
            acc[0] += v.x * w; acc[1] += v.y * w;
            acc[2] += v.z * w; acc[3] += v.w * w;
        }
    }

    const float s = g_s1[co], hh = g_h1[co];
    #pragma unroll
    for (int j = 0; j < 4; j++) {
        int pix = base + pq * 4 + j;
        float y = acc[j] * s + hh;
        y = (y > 0.f) ? y : LEAK * y;
        float y2 = __shfl_down_sync(0xffffffffu, y, 1);   // co+1's value
        if (!(co & 1) && pix < 1444) {
            int h38 = pix / 38, w38 = pix - h38 * 38;
            int cc  = ((h38 & 1) * 2 + (w38 & 1)) * 64 + co;
            int gp  = b * HW + (h38 >> 1) * H19 + (w38 >> 1);
            g_xh2[(size_t)(cc >> 1) * NPIX + gp] = pack2(y, y2);
        }
    }
}

// ---------------- mma.sync helper (fp16, fp32 accum) -------------------------
__device__ __forceinline__ void mma16816(float* d, const unsigned* a, const unsigned* b)
{
    asm volatile(
        "mma.sync.aligned.m16n8k16.row.col.f32.f16.f16.f32 "
        "{%0,%1,%2,%3},{%4,%5,%6,%7},{%8,%9},{%0,%1,%2,%3};"
        : "+f"(d[0]), "+f"(d[1]), "+f"(d[2]), "+f"(d[3])
        : "r"(a[0]), "r"(a[1]), "r"(a[2]), "r"(a[3]), "r"(b[0]), "r"(b[1]));
}

// 32x32 warp tile over K=64 per stage: 2ch x 2kk x 2mi x 4ni = 32 MMAs
__device__ __forceinline__ void mma_tile(const unsigned* A0, const unsigned* A1,
                                         const unsigned* B0, const unsigned* B1,
                                         int wm, int wn, int gid, int tig,
                                         float acc[2][4][4])
{
    #pragma unroll
    for (int ch = 0; ch < 2; ch++) {
        const unsigned* Ac = ch ? A1 : A0;
        const unsigned* Bc = ch ? B1 : B0;
        #pragma unroll
        for (int kk = 0; kk < 2; kk++) {
            const int koff = kk * 8;
            unsigned b[4][2];
            #pragma unroll
            for (int ni = 0; ni < 4; ni++) {
                int col = (wn * 32 + ni * 8 + gid) * SROW + koff + tig;
                b[ni][0] = Bc[col]; b[ni][1] = Bc[col + 4];
            }
            #pragma unroll
            for (int mi = 0; mi < 2; mi++) {
                int r0 = (wm * 32 + mi * 16 + gid) * SROW + koff + tig;
                int r1 = r0 + 8 * SROW;
                unsigned a[4] = {Ac[r0], Ac[r1], Ac[r0 + 4], Ac[r1 + 4]};
                #pragma unroll
                for (int ni = 0; ni < 4; ni++)
                    mma16816(acc[mi][ni], a, b[ni]);
            }
        }
    }
}

// ---------------- conv2 (plain fp16, 512 thr, 16 warps 32x32) ---------------
__global__ __launch_bounds__(512, 2) void conv2_mma()
{
    extern __shared__ unsigned sm[];

    const int tid  = threadIdx.x;
    const int lane = tid & 31;
    const int w    = tid >> 5;            // 0..15
    const int gid  = lane >> 2, tig = lane & 3;
    const int wm   = w >> 2,    wn  = w & 3;   // 4x4 warp grid

    const int co0 = blockIdx.y * 128;
    const int n0  = blockIdx.x * 128;

    // ---- B gather state: 4 threads/pixel, 8 words each ----
    const int bpx  = tid >> 2;            // 0..127
    const int bq   = tid & 3;
    const int pixg = n0 + bpx;
    const bool px_ok = (pixg < NPIX);
    int sp_base = 0;
    unsigned vmask = 0;
    if (px_ok) {
        int bimg = pixg / HW;
        int pix  = pixg - bimg * HW;
        int oh = pix / H19, ow = pix - oh * H19;
        sp_base = bimg * HW + pix;
        #pragma unroll
        for (int r = 0; r < 9; r++) {
            int ih = oh + r / 3 - 1, iw = ow + r % 3 - 1;
            if ((unsigned)ih < 19u && (unsigned)iw < 19u) vmask |= 1u << r;
        }
    }
    int wb = bq * 8, rB = 0;              // word-in-tap (640/tap), tap idx

    // ---- A cp.async: 4 threads/row, 8 words each ----
    const int arow = tid >> 2;
    const int aq   = tid & 3;
    const unsigned* ap = g_w2s + (size_t)(co0 + arow) * KWORD + aq * 8;
    const int adst = (aq < 2 ? AH0w : AH1w) + arow * SROW + (aq & 1) * 8;
    const int bdst = (bq < 2 ? BH0w : BH1w) + bpx * SROW + (bq & 1) * 8;

    float acc[2][4][4];
    #pragma unroll
    for (int mi = 0; mi < 2; mi++)
        #pragma unroll
        for (int ni = 0; ni < 4; ni++)
            #pragma unroll
            for (int e = 0; e < 4; e++) acc[mi][ni][e] = 0.f;

    unsigned fv[8];
    auto gatherB = [&](unsigned* dst) {
        bool val = px_ok && ((vmask >> rB) & 1u);
        int dy  = (rB * 11) >> 5;
        int off = dy * H19 + (rB - dy * 3) - 20;
        const unsigned* p = g_xh2 + (size_t)wb * NPIX + (sp_base + off);
        #pragma unroll
        for (int i = 0; i < 8; i++)
            dst[i] = val ? p[(size_t)i * NPIX] : 0u;
        wb += 32;
        if (wb >= 640) { wb -= 640; ++rB; }
    };
    auto loadA = [&](unsigned* stage, int it) {
        const unsigned* src = ap + it * 32;
        cp16(stage + adst,     src);
        cp16(stage + adst + 4, src + 4);
    };

    loadA(sm, 0);
    cp_commit();
    gatherB(fv);

    const int NIT = KWORD / 32;   // 180
    int s = 0;
    for (int it = 0; it < NIT; it++) {
        unsigned* base = sm + s * STG;
        {
            uint4* bd = (uint4*)(base + bdst);
            bd[0] = make_uint4(fv[0], fv[1], fv[2], fv[3]);
            bd[1] = make_uint4(fv[4], fv[5], fv[6], fv[7]);
        }
        cp_wait0();
        __syncthreads();

        if (it + 1 < NIT) {
            loadA(sm + (s ^ 1) * STG, it + 1);
            cp_commit();
            gatherB(fv);
        }

        mma_tile(base + AH0w, base + AH1w, base + BH0w, base + BH1w,
                 wm, wn, gid, tig, acc);
        s ^= 1;
    }

    // epilogue: BN + leaky -> g_ps2 channel-paired fp16
    #pragma unroll
    for (int mi = 0; mi < 2; mi++) {
        int coA = co0 + wm * 32 + mi * 16 + gid;
        int coB = coA + 8;
        float sA = g_s2[coA], hA = g_h2[coA];
        float sB = g_s2[coB], hB = g_h2[coB];
        #pragma unroll
        for (int ni = 0; ni < 4; ni++) {
            int pg = n0 + wn * 32 + ni * 8 + 2 * tig;
            #pragma unroll
            for (int e = 0; e < 2; e++) {
                int p = pg + e;
                float y = acc[mi][ni][e] * sA + hA;
                y = (y > 0.f) ? y : LEAK * y;
                float z = acc[mi][ni][2 + e] * sB + hB;
                z = (z > 0.f) ? z : LEAK * z;
                float y2 = __shfl_down_sync(0xffffffffu, y, 4);  // gid+1 -> co+1
                float z2 = __shfl_down_sync(0xffffffffu, z, 4);
                if (!(gid & 1) && p < NPIX) {
                    g_ps2[(size_t)(coA >> 1) * NPIX + p] = pack2(y, y2);
                    g_ps2[(size_t)(coB >> 1) * NPIX + p] = pack2(z, z2);
                }
            }
        }
    }
}

// ---------------- det head GEMM (same structure) ----------------------------
__global__ __launch_bounds__(512, 2) void det_mma(float* __restrict__ out)
{
    extern __shared__ unsigned sm[];

    const int tid  = threadIdx.x;
    const int lane = tid & 31;
    const int w    = tid >> 5;
    const int gid  = lane >> 2, tig = lane & 3;
    const int wm   = w >> 2,    wn  = w & 3;

    const int m0 = blockIdx.y * 128;
    const int n0 = blockIdx.x * 128;

    const int bpx  = tid >> 2;
    const int bq   = tid & 3;
    const int pixg = n0 + bpx;
    const bool px_ok = (pixg < NPIX);
    const unsigned* pb = g_ps2 + (size_t)(bq * 8) * NPIX + (px_ok ? pixg : 0);

    const int arow = tid >> 2;
    const int aq   = tid & 3;
    const unsigned* ap = g_rws + (size_t)(m0 + arow) * 512 + aq * 8;
    const int adst = (aq < 2 ? AH0w : AH1w) + arow * SROW + (aq & 1) * 8;
    const int bdst = (bq < 2 ? BH0w : BH1w) + bpx * SROW + (bq & 1) * 8;

    float acc[2][4][4];
    #pragma unroll
    for (int mi = 0; mi < 2; mi++)
        #pragma unroll
        for (int ni = 0; ni < 4; ni++)
            #pragma unroll
            for (int e = 0; e < 4; e++) acc[mi][ni][e] = 0.f;

    unsigned fv[8];
    auto gatherB = [&](unsigned* dst, int it) {
        const unsigned* p = pb + (size_t)(it * 32) * NPIX;
        #pragma unroll
        for (int i = 0; i < 8; i++)
            dst[i] = px_ok ? p[(size_t)i * NPIX] : 0u;
    };
    auto loadA = [&](unsigned* stage, int it) {
        const unsigned* src = ap + it * 32;
        cp16(stage + adst,     src);
        cp16(stage + adst + 4, src + 4);
    };

    loadA(sm, 0);
    cp_commit();
    gatherB(fv, 0);

    const int NIT = 512 / 32;   // 16
    int s = 0;
    for (int it = 0; it < NIT; it++) {
        unsigned* base = sm + s * STG;
        {
            uint4* bd = (uint4*)(base + bdst);
            bd[0] = make_uint4(fv[0], fv[1], fv[2], fv[3]);
            bd[1] = make_uint4(fv[4], fv[5], fv[6], fv[7]);
        }
        cp_wait0();
        __syncthreads();

        if (it + 1 < NIT) {
            loadA(sm + (s ^ 1) * STG, it + 1);
            cp_commit();
            gatherB(fv, it + 1);
        }

        mma_tile(base + AH0w, base + AH1w, base + BH0w, base + BH1w,
                 wm, wn, gid, tig, acc);
        s ^= 1;
    }

    #pragma unroll
    for (int mi = 0; mi < 2; mi++) {
        int mA = m0 + wm * 32 + mi * 16 + gid;
        int mB = mA + 8;
        float cA = (mA < KO) ? g_cb[mA] : 0.f;
        float cB2 = (mB < KO) ? g_cb[mB] : 0.f;
        #pragma unroll
        for (int ni = 0; ni < 4; ni++) {
            int pg = n0 + wn * 32 + ni * 8 + 2 * tig;
            #pragma unroll
            for (int e = 0; e < 2; e++) {
                int p = pg + e;
                if (p < NPIX) {
                    int b = p / HW, pp = p - b * HW;
                    if (mA < KO)
                        out[((size_t)b * KO + mA) * HW + pp] = acc[mi][ni][e] + cA;
                    if (mB < KO)
                        out[((size_t)b * KO + mB) * HW + pp] = acc[mi][ni][2 + e] + cB2;
                }
            }
        }
    }
}

// ---------------- launch ----------------------------------------------------
extern "C" void kernel_launch(void* const* d_in, const int* in_sizes, int n_in,
                              void* d_out, int out_size)
{
    const float* feat0 = (const float*)d_in[0];
    const float* feat1 = (const float*)d_in[1];
    const float* w1    = (const float*)d_in[2];
    const float* g1    = (const float*)d_in[3];
    const float* b1    = (const float*)d_in[4];
    const float* m1    = (const float*)d_in[5];
    const float* v1    = (const float*)d_in[6];
    const float* w2    = (const float*)d_in[7];
    const float* g2    = (const float*)d_in[8];
    const float* b2    = (const float*)d_in[9];
    const float* m2    = (const float*)d_in[10];
    const float* v2    = (const float*)d_in[11];
    const float* rw    = (const float*)d_in[12];
    float* out = (float*)d_out;

    cudaFuncSetAttribute(conv2_mma, cudaFuncAttributeMaxDynamicSharedMemorySize, SMEMB);
    cudaFuncSetAttribute(det_mma,   cudaFuncAttributeMaxDynamicSharedMemorySize, SMEMB);

    prep_kernel<<<23040, 256>>>(w1, g1, b1, m1, v1, g2, b2, m2, v2, rw, w2);
    feat0_split<<<46208, 256>>>(feat0);
    conv1_kernel<<<dim3(91, NB), 256>>>(feat1);
    conv2_mma<<<dim3(181, 8), 512, SMEMB>>>();
    det_mma  <<<dim3(181, 5), 512, SMEMB>>>(out);
}

// round 13
// speedup vs baseline: 1.2316x; 1.2316x over previous
#include <cuda_runtime.h>
#include <cuda_fp16.h>

#define LEAK  0.1f
#define BNEPS 1e-5f

#define NB    64
#define HW    361            // 19*19
#define H19   19
#define C2IN  1280
#define C2K   11520          // 1280*9 (fp16 K total)
#define KWORD 5760           // C2K/2 u32 words per weight row
#define KO    600
#define KOP   640
#define NPIX  (NB * HW)      // 23104

#define SROW  20             // smem row stride in u32 (80 B)
#define AH0w  0
#define AH1w  2560
#define BH0w  5120
#define BH1w  7680
#define STG   10240          // u32 per stage
#define STGB  40960u
#define SMEMB (2 * STG * 4)  // 81920 bytes

// ---------------- device scratch ----------------
__device__ float g_w1t[512 * 64];
__device__ float g_s1[64],  g_h1[64];
__device__ float g_s2[1024], g_h2[1024];
__device__ float g_cb[KO];
__device__ unsigned g_xh2[(size_t)(C2IN / 2) * NPIX];  // conv2 input, ch-paired fp16
__device__ unsigned g_ps2[(size_t)512 * NPIX];         // det input, ch-paired fp16
__device__ __align__(16) unsigned g_w2s[(size_t)1024 * KWORD]; // w2 pairs, K-order r*1280+c
__device__ __align__(16) unsigned g_rws[(size_t)KOP * 512];

__device__ __forceinline__ unsigned pack2(float lo, float hi)
{
    __half2 h = __floats2half2_rn(lo, hi);
    return *reinterpret_cast<unsigned*>(&h);
}

// ---------------- cp.async helpers ----------------
__device__ __forceinline__ void cp16(void* smem, const void* g)
{
    unsigned sa = (unsigned)__cvta_generic_to_shared(smem);
    asm volatile("cp.async.cg.shared.global [%0], [%1], 16;\n" :: "r"(sa), "l"(g));
}
__device__ __forceinline__ void cp_commit() { asm volatile("cp.async.commit_group;\n"); }
__device__ __forceinline__ void cp_wait0()  { asm volatile("cp.async.wait_group 0;\n"); }

// ---------------- prep (small tensors) ----------------
__global__ void prep_kernel(const float* __restrict__ w1,
                            const float* __restrict__ g1, const float* __restrict__ b1,
                            const float* __restrict__ m1, const float* __restrict__ v1,
                            const float* __restrict__ g2, const float* __restrict__ b2,
                            const float* __restrict__ m2, const float* __restrict__ v2,
                            const float* __restrict__ rw)
{
    int i = blockIdx.x * blockDim.x + threadIdx.x;
    if (i < KOP * 512) {
        int m = i >> 9, j = i & 511;
        float x0 = (m < KO) ? rw[m * 1025 + 2 * j]     : 0.f;
        float x1 = (m < KO) ? rw[m * 1025 + 2 * j + 1] : 0.f;
        g_rws[i] = pack2(x0, x1);
    }
    if (i < 512 * 64) {
        int k = i >> 6, co = i & 63;
        g_w1t[i] = w1[co * 512 + k];
    }
    if (i < KO)   g_cb[i] = rw[i * 1025 + 1024];
    if (i < 64)   { float s = g1[i] * rsqrtf(v1[i] + BNEPS); g_s1[i] = s; g_h1[i] = b1[i] - m1[i] * s; }
    if (i < 1024) { float s = g2[i] * rsqrtf(v2[i] + BNEPS); g_s2[i] = s; g_h2[i] = b2[i] - m2[i] * s; }
}

// ---------------- prep w2: coalesced transpose via smem row stage -----------
__global__ __launch_bounds__(256) void prep_w2(const float* __restrict__ w2)
{
    __shared__ float row[C2K];        // 46080 B
    const int co = blockIdx.x;
    const float* src = w2 + (size_t)co * C2K;
    for (int i = threadIdx.x; i < C2K; i += 256) row[i] = src[i];
    __syncthreads();
    unsigned* dst = g_w2s + (size_t)co * KWORD;
    for (int j = threadIdx.x; j < KWORD; j += 256) {
        int r = j / 640;
        int c = (j - r * 640) * 2;
        dst[j] = pack2(row[c * 9 + r], row[c * 9 + 9 + r]);
    }
}

// ---------------- feat0 -> g_xh2 channel-pairs 128..639 ----------------
__global__ void feat0_split(const float* __restrict__ feat0)
{
    long long i = (long long)blockIdx.x * blockDim.x + threadIdx.x;
    if (i < (long long)NB * 512 * HW) {
        int hw = (int)(i % HW);
        long long t = i / HW;
        int cp = (int)(t & 511);
        int b  = (int)(t >> 9);
        const float* src = feat0 + ((size_t)b * 1024 + 2 * cp) * HW + hw;
        g_xh2[(size_t)(128 + cp) * NPIX + b * HW + hw] = pack2(src[0], src[HW]);
    }
}

// ---------------- conv1 (1x1, 512->64) + BN + leaky + reorg(2) --------------
__global__ __launch_bounds__(256) void conv1_kernel(const float* __restrict__ feat1)
{
    __shared__ __align__(16) float s_in[512][16];
    __shared__ float s_w[64][64];

    const int b    = blockIdx.y;
    const int base = blockIdx.x * 16;
    const float* f = feat1 + (size_t)b * 512 * 1444;

    for (int idx = threadIdx.x; idx < 512 * 16; idx += 256) {
        int p = idx & 15, k = idx >> 4;
        int pix = base + p;
        s_in[k][p] = (pix < 1444) ? f[k * 1444 + pix] : 0.f;
    }

    const int co = threadIdx.x & 63;
    const int pq = threadIdx.x >> 6;
    float acc[4] = {0.f, 0.f, 0.f, 0.f};

    for (int kc = 0; kc < 512; kc += 64) {
        __syncthreads();
        for (int idx = threadIdx.x; idx < 64 * 64; idx += 256)
            s_w[idx >> 6][idx & 63] = g_w1t[(kc + (idx >> 6)) * 64 + (idx & 63)];
        __syncthreads();
        #pragma unroll
        for (int kk = 0; kk < 64; kk++) {
            float  w = s_w[kk][co];
            float4 v = *(const float4*)&s_in[kc + kk][pq * 4];
            acc[0] += v.x * w; acc[1] += v.y * w;
            acc[2] += v.z * w; acc[3] += v.w * w;
        }
    }

    const float s = g_s1[co], hh = g_h1[co];
    #pragma unroll
    for (int j = 0; j < 4; j++) {
        int pix = base + pq * 4 + j;
        float y = acc[j] * s + hh;
        y = (y > 0.f) ? y : LEAK * y;
        float y2 = __shfl_down_sync(0xffffffffu, y, 1);
        if (!(co & 1) && pix < 1444) {
            int h38 = pix / 38, w38 = pix - h38 * 38;
            int cc  = ((h38 & 1) * 2 + (w38 & 1)) * 64 + co;
            int gp  = b * HW + (h38 >> 1) * H19 + (w38 >> 1);
            g_xh2[(size_t)(cc >> 1) * NPIX + gp] = pack2(y, y2);
        }
    }
}

// ---------------- mma / ldmatrix helpers ----------------
__device__ __forceinline__ void mma16816(float* d, const unsigned* a, const unsigned* b)
{
    asm volatile(
        "mma.sync.aligned.m16n8k16.row.col.f32.f16.f16.f32 "
        "{%0,%1,%2,%3},{%4,%5,%6,%7},{%8,%9},{%0,%1,%2,%3};"
        : "+f"(d[0]), "+f"(d[1]), "+f"(d[2]), "+f"(d[3])
        : "r"(a[0]), "r"(a[1]), "r"(a[2]), "r"(a[3]), "r"(b[0]), "r"(b[1]));
}

__device__ __forceinline__ void ldsm4(unsigned& r0, unsigned& r1, unsigned& r2, unsigned& r3,
                                      unsigned saddr)
{
    asm volatile("ldmatrix.sync.aligned.m8n8.x4.shared.b16 {%0,%1,%2,%3}, [%4];"
                 : "=r"(r0), "=r"(r1), "=r"(r2), "=r"(r3) : "r"(saddr));
}

// 64x32 warp tile, K=64/stage, software-pipelined fragments (B per-group,
// A per-mi double buffer). ldmatrix mapping verified in R9 on this layout.
__device__ __forceinline__ void mma_tile(unsigned sb, unsigned aoff, unsigned boff,
                                         float acc[4][4][4])
{
    const unsigned ABASE[4] = { sb + aoff,            sb + aoff + 32u,
                                sb + 10240u + aoff,   sb + 10240u + aoff + 32u };
    const unsigned BBASE[4] = { sb + 20480u + boff,   sb + 20480u + boff + 32u,
                                sb + 30720u + boff,   sb + 30720u + boff + 32u };

    unsigned bfr[2][4][2];
    unsigned afr[2][4];

    // prologue: B group0, A mi0
    ldsm4(bfr[0][0][0], bfr[0][1][0], bfr[0][0][1], bfr[0][1][1], BBASE[0]);
    ldsm4(bfr[0][2][0], bfr[0][3][0], bfr[0][2][1], bfr[0][3][1], BBASE[0] + 1280u);
    ldsm4(afr[0][0], afr[0][1], afr[0][2], afr[0][3], ABASE[0]);

    #pragma unroll
    for (int g = 0; g < 4; g++) {
        const int bc = g & 1;
        #pragma unroll
        for (int mi = 0; mi < 4; mi++) {
            const int ac = mi & 1;
            if (mi < 3) {
                ldsm4(afr[ac ^ 1][0], afr[ac ^ 1][1], afr[ac ^ 1][2], afr[ac ^ 1][3],
                      ABASE[g] + (mi + 1) * 1280u);
            } else if (g < 3) {
                ldsm4(bfr[bc ^ 1][0][0], bfr[bc ^ 1][1][0], bfr[bc ^ 1][0][1], bfr[bc ^ 1][1][1],
                      BBASE[g + 1]);
                ldsm4(bfr[bc ^ 1][2][0], bfr[bc ^ 1][3][0], bfr[bc ^ 1][2][1], bfr[bc ^ 1][3][1],
                      BBASE[g + 1] + 1280u);
                ldsm4(afr[ac ^ 1][0], afr[ac ^ 1][1], afr[ac ^ 1][2], afr[ac ^ 1][3],
                      ABASE[g + 1]);
            }
            #pragma unroll
            for (int ni = 0; ni < 4; ni++)
                mma16816(acc[mi][ni], afr[ac], bfr[bc][ni]);
        }
    }
}

// ---------------- conv2 (plain fp16, 256 thr, 8 warps 64x32, pipelined) -----
__global__ __launch_bounds__(256, 2) void conv2_mma()
{
    extern __shared__ unsigned sm[];
    const unsigned smb = (unsigned)__cvta_generic_to_shared(sm);

    const int tid  = threadIdx.x;
    const int lane = tid & 31;
    const int w    = tid >> 5;
    const int gid  = lane >> 2, tig = lane & 3;
    const int wm   = w >> 2,    wn  = w & 3;     // 2x4 warp grid

    const int co0 = blockIdx.y * 128;
    const int n0  = blockIdx.x * 128;

    // ---- B gather state ----
    const int bpx  = tid >> 1;
    const int kq   = (tid & 1) * 16;
    const int pixg = n0 + bpx;
    const bool px_ok = (pixg < NPIX);
    int sp_base = 0;
    unsigned vmask = 0;
    if (px_ok) {
        int bimg = pixg / HW;
        int pix  = pixg - bimg * HW;
        int oh = pix / H19, ow = pix - oh * H19;
        sp_base = bimg * HW + pix;
        #pragma unroll
        for (int r = 0; r < 9; r++) {
            int ih = oh + r / 3 - 1, iw = ow + r % 3 - 1;
            if ((unsigned)ih < 19u && (unsigned)iw < 19u) vmask |= 1u << r;
        }
    }
    int wb = kq, rB = 0;

    // ---- A cp.async mapping ----
    const int arow  = tid >> 1;
    const int ahalf = tid & 1;
    const unsigned* ap = g_w2s + (size_t)(co0 + arow) * KWORD + ahalf * 8;
    const int adst = arow * SROW + ahalf * 8;
    const int bdst = (kq ? BH1w : BH0w) + bpx * SROW;

    // ldmatrix per-thread offsets (bytes)
    const unsigned aoff = (unsigned)((wm * 64 + (lane & 15)) * 80 + (lane >> 4) * 16);
    const unsigned boff = (unsigned)((wn * 32 + (lane & 15)) * 80 + (lane >> 4) * 16);

    float acc[4][4][4];
    #pragma unroll
    for (int mi = 0; mi < 4; mi++)
        #pragma unroll
        for (int ni = 0; ni < 4; ni++)
            #pragma unroll
            for (int e = 0; e < 4; e++) acc[mi][ni][e] = 0.f;

    unsigned fv[16];
    auto gatherB = [&](unsigned* dst) {
        bool val = px_ok && ((vmask >> rB) & 1u);
        int dy  = (rB * 11) >> 5;
        int off = dy * H19 + (rB - dy * 3) - 20;
        const unsigned* p = g_xh2 + (size_t)wb * NPIX + (sp_base + off);
        #pragma unroll
        for (int i = 0; i < 16; i++)
            dst[i] = val ? p[(size_t)i * NPIX] : 0u;
        wb += 32;
        if (wb >= 640) { wb -= 640; ++rB; }
    };
    auto loadA = [&](unsigned* stage, int it) {
        const unsigned* src = ap + it * 32;
        cp16(stage + AH0w + adst,     src);
        cp16(stage + AH0w + adst + 4, src + 4);
        cp16(stage + AH1w + adst,     src + 16);
        cp16(stage + AH1w + adst + 4, src + 20);
    };

    loadA(sm, 0);
    cp_commit();
    gatherB(fv);

    const int NIT = KWORD / 32;   // 180
    int s = 0;
    for (int it = 0; it < NIT; it++) {
        unsigned* base = sm + s * STG;
        {
            uint4* bd = (uint4*)(base + bdst);
            bd[0] = make_uint4(fv[0],  fv[1],  fv[2],  fv[3]);
            bd[1] = make_uint4(fv[4],  fv[5],  fv[6],  fv[7]);
            bd[2] = make_uint4(fv[8],  fv[9],  fv[10], fv[11]);
            bd[3] = make_uint4(fv[12], fv[13], fv[14], fv[15]);
        }
        cp_wait0();
        __syncthreads();

        if (it + 1 < NIT) {
            loadA(sm + (s ^ 1) * STG, it + 1);
            cp_commit();
            gatherB(fv);    // overlaps MMAs below
        }

        mma_tile(smb + (unsigned)s * STGB, aoff, boff, acc);
        s ^= 1;
    }

    // epilogue: BN + leaky -> g_ps2 channel-paired fp16
    #pragma unroll
    for (int mi = 0; mi < 4; mi++) {
        int coA = co0 + wm * 64 + mi * 16 + gid;
        int coB = coA + 8;
        float sA = g_s2[coA], hA = g_h2[coA];
        float sB = g_s2[coB], hB = g_h2[coB];
        #pragma unroll
        for (int ni = 0; ni < 4; ni++) {
            int pg = n0 + wn * 32 + ni * 8 + 2 * tig;
            #pragma unroll
            for (int e = 0; e < 2; e++) {
                int p = pg + e;
                float y = acc[mi][ni][e] * sA + hA;
                y = (y > 0.f) ? y : LEAK * y;
                float z = acc[mi][ni][2 + e] * sB + hB;
                z = (z > 0.f) ? z : LEAK * z;
                float y2 = __shfl_down_sync(0xffffffffu, y, 4);
                float z2 = __shfl_down_sync(0xffffffffu, z, 4);
                if (!(gid & 1) && p < NPIX) {
                    g_ps2[(size_t)(coA >> 1) * NPIX + p] = pack2(y, y2);
                    g_ps2[(size_t)(coB >> 1) * NPIX + p] = pack2(z, z2);
                }
            }
        }
    }
}

// ---------------- det head GEMM (same structure) ----------------------------
__global__ __launch_bounds__(256, 2) void det_mma(float* __restrict__ out)
{
    extern __shared__ unsigned sm[];
    const unsigned smb = (unsigned)__cvta_generic_to_shared(sm);

    const int tid  = threadIdx.x;
    const int lane = tid & 31;
    const int w    = tid >> 5;
    const int gid  = lane >> 2, tig = lane & 3;
    const int wm   = w >> 2,    wn  = w & 3;

    const int m0 = blockIdx.y * 128;
    const int n0 = blockIdx.x * 128;

    const int bpx  = tid >> 1;
    const int kq   = (tid & 1) * 16;
    const int pixg = n0 + bpx;
    const bool px_ok = (pixg < NPIX);
    const unsigned* pb = g_ps2 + (size_t)kq * NPIX + (px_ok ? pixg : 0);

    const int arow  = tid >> 1;
    const int ahalf = tid & 1;
    const unsigned* ap = g_rws + (size_t)(m0 + arow) * 512 + ahalf * 8;
    const int adst = arow * SROW + ahalf * 8;
    const int bdst = (kq ? BH1w : BH0w) + bpx * SROW;

    const unsigned aoff = (unsigned)((wm * 64 + (lane & 15)) * 80 + (lane >> 4) * 16);
    const unsigned boff = (unsigned)((wn * 32 + (lane & 15)) * 80 + (lane >> 4) * 16);

    float acc[4][4][4];
    #pragma unroll
    for (int mi = 0; mi < 4; mi++)
        #pragma unroll
        for (int ni = 0; ni < 4; ni++)
            #pragma unroll
            for (int e = 0; e < 4; e++) acc[mi][ni][e] = 0.f;

    unsigned fv[16];
    auto gatherB = [&](unsigned* dst, int it) {
        const unsigned* p = pb + (size_t)(it * 32) * NPIX;
        #pragma unroll
        for (int i = 0; i < 16; i++)
            dst[i] = px_ok ? p[(size_t)i * NPIX] : 0u;
    };
    auto loadA = [&](unsigned* stage, int it) {
        const unsigned* src = ap + it * 32;
        cp16(stage + AH0w + adst,     src);
        cp16(stage + AH0w + adst + 4, src + 4);
        cp16(stage + AH1w + adst,     src + 16);
        cp16(stage + AH1w + adst + 4, src + 20);
    };

    loadA(sm, 0);
    cp_commit();
    gatherB(fv, 0);

    const int NIT = 512 / 32;   // 16
    int s = 0;
    for (int it = 0; it < NIT; it++) {
        unsigned* base = sm + s * STG;
        {
            uint4* bd = (uint4*)(base + bdst);
            bd[0] = make_uint4(fv[0],  fv[1],  fv[2],  fv[3]);
            bd[1] = make_uint4(fv[4],  fv[5],  fv[6],  fv[7]);
            bd[2] = make_uint4(fv[8],  fv[9],  fv[10], fv[11]);
            bd[3] = make_uint4(fv[12], fv[13], fv[14], fv[15]);
        }
        cp_wait0();
        __syncthreads();

        if (it + 1 < NIT) {
            loadA(sm + (s ^ 1) * STG, it + 1);
            cp_commit();
            gatherB(fv, it + 1);
        }

        mma_tile(smb + (unsigned)s * STGB, aoff, boff, acc);
        s ^= 1;
    }

    #pragma unroll
    for (int mi = 0; mi < 4; mi++) {
        int mA = m0 + wm * 64 + mi * 16 + gid;
        int mB = mA + 8;
        float cA = (mA < KO) ? g_cb[mA] : 0.f;
        float cB2 = (mB < KO) ? g_cb[mB] : 0.f;
        #pragma unroll
        for (int ni = 0; ni < 4; ni++) {
            int pg = n0 + wn * 32 + ni * 8 + 2 * tig;
            #pragma unroll
            for (int e = 0; e < 2; e++) {
                int p = pg + e;
                if (p < NPIX) {
                    int b = p / HW, pp = p - b * HW;
                    if (mA < KO)
                        out[((size_t)b * KO + mA) * HW + pp] = acc[mi][ni][e] + cA;
                    if (mB < KO)
                        out[((size_t)b * KO + mB) * HW + pp] = acc[mi][ni][2 + e] + cB2;
                }
            }
        }
    }
}

// ---------------- launch ----------------------------------------------------
extern "C" void kernel_launch(void* const* d_in, const int* in_sizes, int n_in,
                              void* d_out, int out_size)
{
    const float* feat0 = (const float*)d_in[0];
    const float* feat1 = (const float*)d_in[1];
    const float* w1    = (const float*)d_in[2];
    const float* g1    = (const float*)d_in[3];
    const float* b1    = (const float*)d_in[4];
    const float* m1    = (const float*)d_in[5];
    const float* v1    = (const float*)d_in[6];
    const float* w2    = (const float*)d_in[7];
    const float* g2    = (const float*)d_in[8];
    const float* b2    = (const float*)d_in[9];
    const float* m2    = (const float*)d_in[10];
    const float* v2    = (const float*)d_in[11];
    const float* rw    = (const float*)d_in[12];
    float* out = (float*)d_out;

    cudaFuncSetAttribute(conv2_mma, cudaFuncAttributeMaxDynamicSharedMemorySize, SMEMB);
    cudaFuncSetAttribute(det_mma,   cudaFuncAttributeMaxDynamicSharedMemorySize, SMEMB);

    prep_kernel<<<1280, 256>>>(w1, g1, b1, m1, v1, g2, b2, m2, v2, rw);
    prep_w2<<<1024, 256>>>(w2);
    feat0_split<<<46208, 256>>>(feat0);
    conv1_kernel<<<dim3(91, NB), 256>>>(feat1);
    conv2_mma<<<dim3(181, 8), 256, SMEMB>>>();
    det_mma  <<<dim3(181, 5), 256, SMEMB>>>(out);
}

// round 14
// speedup vs baseline: 1.3545x; 1.0998x over previous
#include <cuda_runtime.h>
#include <cuda_fp16.h>

#define LEAK  0.1f
#define BNEPS 1e-5f

#define NB    64
#define HW    361            // 19*19
#define H19   19
#define C2IN  1280
#define C2K   11520          // 1280*9 (fp16 K total)
#define KWORD 5760           // C2K/2 u32 words per weight row
#define KO    600
#define KOP   640
#define NPIX  (NB * HW)      // 23104
#define NPIXF (NB * 1444)    // 92416 (feat1 pixels), divisible by 128

#define SROW  20             // smem row stride in u32 (80 B)
#define AH0w  0
#define AH1w  2560
#define BH0w  5120
#define BH1w  7680
#define STG   10240          // u32 per stage
#define STGB  40960u
#define SMEMB (2 * STG * 4)  // 81920 bytes

// ---------------- device scratch ----------------
__device__ float g_s1[64],  g_h1[64];
__device__ float g_s2[1024], g_h2[1024];
__device__ float g_cb[KO];
__device__ unsigned g_xh2[(size_t)(C2IN / 2) * NPIX];   // conv2 input, ch-paired fp16
__device__ unsigned g_ps2[(size_t)512 * NPIX];          // det input, ch-paired fp16
__device__ unsigned g_xf1[(size_t)256 * NPIXF];         // conv1 input, ch-paired fp16
__device__ __align__(16) unsigned g_w2s[(size_t)1024 * KWORD]; // w2 pairs, K-order r*1280+c
__device__ __align__(16) unsigned g_rws[(size_t)KOP * 512];
__device__ __align__(16) unsigned g_w1s[(size_t)128 * 256];    // w1 pairs (rows 64..127 zero)

__device__ __forceinline__ unsigned pack2(float lo, float hi)
{
    __half2 h = __floats2half2_rn(lo, hi);
    return *reinterpret_cast<unsigned*>(&h);
}

// ---------------- cp.async helpers ----------------
__device__ __forceinline__ void cp16(void* smem, const void* g)
{
    unsigned sa = (unsigned)__cvta_generic_to_shared(smem);
    asm volatile("cp.async.cg.shared.global [%0], [%1], 16;\n" :: "r"(sa), "l"(g));
}
__device__ __forceinline__ void cp_commit() { asm volatile("cp.async.commit_group;\n"); }
__device__ __forceinline__ void cp_wait0()  { asm volatile("cp.async.wait_group 0;\n"); }

// ---------------- prep (small tensors) ----------------
__global__ void prep_kernel(const float* __restrict__ w1,
                            const float* __restrict__ g1, const float* __restrict__ b1,
                            const float* __restrict__ m1, const float* __restrict__ v1,
                            const float* __restrict__ g2, const float* __restrict__ b2,
                            const float* __restrict__ m2, const float* __restrict__ v2,
                            const float* __restrict__ rw)
{
    int i = blockIdx.x * blockDim.x + threadIdx.x;
    if (i < KOP * 512) {
        int m = i >> 9, j = i & 511;
        float x0 = (m < KO) ? rw[m * 1025 + 2 * j]     : 0.f;
        float x1 = (m < KO) ? rw[m * 1025 + 2 * j + 1] : 0.f;
        g_rws[i] = pack2(x0, x1);
    }
    if (i < 128 * 256) {
        int co = i >> 8, j = i & 255;
        float x0 = (co < 64) ? w1[co * 512 + 2 * j]     : 0.f;
        float x1 = (co < 64) ? w1[co * 512 + 2 * j + 1] : 0.f;
        g_w1s[i] = pack2(x0, x1);
    }
    if (i < KO)   g_cb[i] = rw[i * 1025 + 1024];
    if (i < 64)   { float s = g1[i] * rsqrtf(v1[i] + BNEPS); g_s1[i] = s; g_h1[i] = b1[i] - m1[i] * s; }
    if (i < 1024) { float s = g2[i] * rsqrtf(v2[i] + BNEPS); g_s2[i] = s; g_h2[i] = b2[i] - m2[i] * s; }
}

// ---------------- prep w2: coalesced transpose via smem row stage -----------
__global__ __launch_bounds__(256) void prep_w2(const float* __restrict__ w2)
{
    __shared__ float row[C2K];
    const int co = blockIdx.x;
    const float* src = w2 + (size_t)co * C2K;
    for (int i = threadIdx.x; i < C2K; i += 256) row[i] = src[i];
    __syncthreads();
    unsigned* dst = g_w2s + (size_t)co * KWORD;
    for (int j = threadIdx.x; j < KWORD; j += 256) {
        int r = j / 640;
        int c = (j - r * 640) * 2;
        dst[j] = pack2(row[c * 9 + r], row[c * 9 + 9 + r]);
    }
}

// ---------------- feat0 -> g_xh2 channel-pairs 128..639 ----------------
__global__ void feat0_split(const float* __restrict__ feat0)
{
    long long i = (long long)blockIdx.x * blockDim.x + threadIdx.x;
    if (i < (long long)NB * 512 * HW) {
        int hw = (int)(i % HW);
        long long t = i / HW;
        int cp = (int)(t & 511);
        int b  = (int)(t >> 9);
        const float* src = feat0 + ((size_t)b * 1024 + 2 * cp) * HW + hw;
        g_xh2[(size_t)(128 + cp) * NPIX + b * HW + hw] = pack2(src[0], src[HW]);
    }
}

// ---------------- feat1 -> g_xf1 channel-pairs ----------------
__global__ void feat1_split(const float* __restrict__ feat1)
{
    long long i = (long long)blockIdx.x * blockDim.x + threadIdx.x;
    if (i < (long long)NB * 256 * 1444) {
        int hw = (int)(i % 1444);
        long long t = i / 1444;
        int cp = (int)(t & 255);
        int b  = (int)(t >> 8);
        const float* src = feat1 + ((size_t)b * 512 + 2 * cp) * 1444 + hw;
        g_xf1[(size_t)cp * NPIXF + b * 1444 + hw] = pack2(src[0], src[1444]);
    }
}

// ---------------- mma / ldmatrix helpers ----------------
__device__ __forceinline__ void mma16816(float* d, const unsigned* a, const unsigned* b)
{
    asm volatile(
        "mma.sync.aligned.m16n8k16.row.col.f32.f16.f16.f32 "
        "{%0,%1,%2,%3},{%4,%5,%6,%7},{%8,%9},{%0,%1,%2,%3};"
        : "+f"(d[0]), "+f"(d[1]), "+f"(d[2]), "+f"(d[3])
        : "r"(a[0]), "r"(a[1]), "r"(a[2]), "r"(a[3]), "r"(b[0]), "r"(b[1]));
}

__device__ __forceinline__ void ldsm4(unsigned& r0, unsigned& r1, unsigned& r2, unsigned& r3,
                                      unsigned saddr)
{
    asm volatile("ldmatrix.sync.aligned.m8n8.x4.shared.b16 {%0,%1,%2,%3}, [%4];"
                 : "=r"(r0), "=r"(r1), "=r"(r2), "=r"(r3) : "r"(saddr));
}

// 64x32 warp tile, K=64/stage, software-pipelined fragments
__device__ __forceinline__ void mma_tile(unsigned sb, unsigned aoff, unsigned boff,
                                         float acc[4][4][4])
{
    const unsigned ABASE[4] = { sb + aoff,            sb + aoff + 32u,
                                sb + 10240u + aoff,   sb + 10240u + aoff + 32u };
    const unsigned BBASE[4] = { sb + 20480u + boff,   sb + 20480u + boff + 32u,
                                sb + 30720u + boff,   sb + 30720u + boff + 32u };

    unsigned bfr[2][4][2];
    unsigned afr[2][4];

    ldsm4(bfr[0][0][0], bfr[0][1][0], bfr[0][0][1], bfr[0][1][1], BBASE[0]);
    ldsm4(bfr[0][2][0], bfr[0][3][0], bfr[0][2][1], bfr[0][3][1], BBASE[0] + 1280u);
    ldsm4(afr[0][0], afr[0][1], afr[0][2], afr[0][3], ABASE[0]);

    #pragma unroll
    for (int g = 0; g < 4; g++) {
        const int bc = g & 1;
        #pragma unroll
        for (int mi = 0; mi < 4; mi++) {
            const int ac = mi & 1;
            if (mi < 3) {
                ldsm4(afr[ac ^ 1][0], afr[ac ^ 1][1], afr[ac ^ 1][2], afr[ac ^ 1][3],
                      ABASE[g] + (mi + 1) * 1280u);
            } else if (g < 3) {
                ldsm4(bfr[bc ^ 1][0][0], bfr[bc ^ 1][1][0], bfr[bc ^ 1][0][1], bfr[bc ^ 1][1][1],
                      BBASE[g + 1]);
                ldsm4(bfr[bc ^ 1][2][0], bfr[bc ^ 1][3][0], bfr[bc ^ 1][2][1], bfr[bc ^ 1][3][1],
                      BBASE[g + 1] + 1280u);
                ldsm4(afr[ac ^ 1][0], afr[ac ^ 1][1], afr[ac ^ 1][2], afr[ac ^ 1][3],
                      ABASE[g + 1]);
            }
            #pragma unroll
            for (int ni = 0; ni < 4; ni++)
                mma16816(acc[mi][ni], afr[ac], bfr[bc][ni]);
        }
    }
}

// ---------------- conv1 GEMM: M=64(pad128) x K=512 x N=92416 + reorg --------
__global__ __launch_bounds__(256, 2) void conv1_mma()
{
    extern __shared__ unsigned sm[];
    const unsigned smb = (unsigned)__cvta_generic_to_shared(sm);

    const int tid  = threadIdx.x;
    const int lane = tid & 31;
    const int w    = tid >> 5;
    const int gid  = lane >> 2, tig = lane & 3;
    const int wm   = w >> 2,    wn  = w & 3;

    const int n0 = blockIdx.x * 128;

    const int bpx  = tid >> 1;
    const int kq   = (tid & 1) * 16;
    const int pixg = n0 + bpx;                  // always < NPIXF (722*128 exact)
    const unsigned* pb = g_xf1 + (size_t)kq * NPIXF + pixg;

    const int arow  = tid >> 1;
    const int ahalf = tid & 1;
    const unsigned* ap = g_w1s + (size_t)arow * 256 + ahalf * 8;
    const int adst = arow * SROW + ahalf * 8;
    const int bdst = (kq ? BH1w : BH0w) + bpx * SROW;

    const unsigned aoff = (unsigned)((wm * 64 + (lane & 15)) * 80 + (lane >> 4) * 16);
    const unsigned boff = (unsigned)((wn * 32 + (lane & 15)) * 80 + (lane >> 4) * 16);

    float acc[4][4][4];
    #pragma unroll
    for (int mi = 0; mi < 4; mi++)
        #pragma unroll
        for (int ni = 0; ni < 4; ni++)
            #pragma unroll
            for (int e = 0; e < 4; e++) acc[mi][ni][e] = 0.f;

    unsigned fv[16];
    auto gatherB = [&](unsigned* dst, int it) {
        const unsigned* p = pb + (size_t)(it * 32) * NPIXF;
        #pragma unroll
        for (int i = 0; i < 16; i++)
            dst[i] = p[(size_t)i * NPIXF];
    };
    auto loadA = [&](unsigned* stage, int it) {
        const unsigned* src = ap + it * 32;
        cp16(stage + AH0w + adst,     src);
        cp16(stage + AH0w + adst + 4, src + 4);
        cp16(stage + AH1w + adst,     src + 16);
        cp16(stage + AH1w + adst + 4, src + 20);
    };

    loadA(sm, 0);
    cp_commit();
    gatherB(fv, 0);

    const int NIT = 256 / 32;   // 8
    int s = 0;
    for (int it = 0; it < NIT; it++) {
        unsigned* base = sm + s * STG;
        {
            uint4* bd = (uint4*)(base + bdst);
            bd[0] = make_uint4(fv[0],  fv[1],  fv[2],  fv[3]);
            bd[1] = make_uint4(fv[4],  fv[5],  fv[6],  fv[7]);
            bd[2] = make_uint4(fv[8],  fv[9],  fv[10], fv[11]);
            bd[3] = make_uint4(fv[12], fv[13], fv[14], fv[15]);
        }
        cp_wait0();
        __syncthreads();

        if (it + 1 < NIT) {
            loadA(sm + (s ^ 1) * STG, it + 1);
            cp_commit();
            gatherB(fv, it + 1);
        }

        mma_tile(smb + (unsigned)s * STGB, aoff, boff, acc);
        s ^= 1;
    }

    // epilogue: only wm==0 rows (co 0..63) valid; BN + leaky + reorg scatter
    if (wm == 0) {
        #pragma unroll
        for (int mi = 0; mi < 4; mi++) {
            int coA = mi * 16 + gid;
            int coB = coA + 8;
            float sA = g_s1[coA], hA = g_h1[coA];
            float sB = g_s1[coB], hB = g_h1[coB];
            #pragma unroll
            for (int ni = 0; ni < 4; ni++) {
                int pg = n0 + wn * 32 + ni * 8 + 2 * tig;
                #pragma unroll
                for (int e = 0; e < 2; e++) {
                    int p = pg + e;
                    float y = acc[mi][ni][e] * sA + hA;
                    y = (y > 0.f) ? y : LEAK * y;
                    float z = acc[mi][ni][2 + e] * sB + hB;
                    z = (z > 0.f) ? z : LEAK * z;
                    float y2 = __shfl_down_sync(0xffffffffu, y, 4);
                    float z2 = __shfl_down_sync(0xffffffffu, z, 4);
                    if (!(gid & 1)) {
                        int b   = p / 1444, pix = p - b * 1444;
                        int h38 = pix / 38,  w38 = pix - h38 * 38;
                        int quad = (h38 & 1) * 2 + (w38 & 1);
                        int gp  = b * HW + (h38 >> 1) * H19 + (w38 >> 1);
                        int ccA = quad * 64 + coA;
                        int ccB = quad * 64 + coB;
                        g_xh2[(size_t)(ccA >> 1) * NPIX + gp] = pack2(y, y2);
                        g_xh2[(size_t)(ccB >> 1) * NPIX + gp] = pack2(z, z2);
                    }
                }
            }
        }
    }
}

// ---------------- conv2 (plain fp16, 256 thr, 8 warps 64x32, pipelined) -----
__global__ __launch_bounds__(256, 2) void conv2_mma()
{
    extern __shared__ unsigned sm[];
    const unsigned smb = (unsigned)__cvta_generic_to_shared(sm);

    const int tid  = threadIdx.x;
    const int lane = tid & 31;
    const int w    = tid >> 5;
    const int gid  = lane >> 2, tig = lane & 3;
    const int wm   = w >> 2,    wn  = w & 3;

    const int co0 = blockIdx.y * 128;
    const int n0  = blockIdx.x * 128;

    const int bpx  = tid >> 1;
    const int kq   = (tid & 1) * 16;
    const int pixg = n0 + bpx;
    const bool px_ok = (pixg < NPIX);
    int sp_base = 0;
    unsigned vmask = 0;
    if (px_ok) {
        int bimg = pixg / HW;
        int pix  = pixg - bimg * HW;
        int oh = pix / H19, ow = pix - oh * H19;
        sp_base = bimg * HW + pix;
        #pragma unroll
        for (int r = 0; r < 9; r++) {
            int ih = oh + r / 3 - 1, iw = ow + r % 3 - 1;
            if ((unsigned)ih < 19u && (unsigned)iw < 19u) vmask |= 1u << r;
        }
    }
    int wb = kq, rB = 0;

    const int arow  = tid >> 1;
    const int ahalf = tid & 1;
    const unsigned* ap = g_w2s + (size_t)(co0 + arow) * KWORD + ahalf * 8;
    const int adst = arow * SROW + ahalf * 8;
    const int bdst = (kq ? BH1w : BH0w) + bpx * SROW;

    const unsigned aoff = (unsigned)((wm * 64 + (lane & 15)) * 80 + (lane >> 4) * 16);
    const unsigned boff = (unsigned)((wn * 32 + (lane & 15)) * 80 + (lane >> 4) * 16);

    float acc[4][4][4];
    #pragma unroll
    for (int mi = 0; mi < 4; mi++)
        #pragma unroll
        for (int ni = 0; ni < 4; ni++)
            #pragma unroll
            for (int e = 0; e < 4; e++) acc[mi][ni][e] = 0.f;

    unsigned fv[16];
    auto gatherB = [&](unsigned* dst) {
        bool val = px_ok && ((vmask >> rB) & 1u);
        int dy  = (rB * 11) >> 5;
        int off = dy * H19 + (rB - dy * 3) - 20;
        const unsigned* p = g_xh2 + (size_t)wb * NPIX + (sp_base + off);
        #pragma unroll
        for (int i = 0; i < 16; i++)
            dst[i] = val ? p[(size_t)i * NPIX] : 0u;
        wb += 32;
        if (wb >= 640) { wb -= 640; ++rB; }
    };
    auto loadA = [&](unsigned* stage, int it) {
        const unsigned* src = ap + it * 32;
        cp16(stage + AH0w + adst,     src);
        cp16(stage + AH0w + adst + 4, src + 4);
        cp16(stage + AH1w + adst,     src + 16);
        cp16(stage + AH1w + adst + 4, src + 20);
    };

    loadA(sm, 0);
    cp_commit();
    gatherB(fv);

    const int NIT = KWORD / 32;   // 180
    int s = 0;
    for (int it = 0; it < NIT; it++) {
        unsigned* base = sm + s * STG;
        {
            uint4* bd = (uint4*)(base + bdst);
            bd[0] = make_uint4(fv[0],  fv[1],  fv[2],  fv[3]);
            bd[1] = make_uint4(fv[4],  fv[5],  fv[6],  fv[7]);
            bd[2] = make_uint4(fv[8],  fv[9],  fv[10], fv[11]);
            bd[3] = make_uint4(fv[12], fv[13], fv[14], fv[15]);
        }
        cp_wait0();
        __syncthreads();

        if (it + 1 < NIT) {
            loadA(sm + (s ^ 1) * STG, it + 1);
            cp_commit();
            gatherB(fv);
        }

        mma_tile(smb + (unsigned)s * STGB, aoff, boff, acc);
        s ^= 1;
    }

    #pragma unroll
    for (int mi = 0; mi < 4; mi++) {
        int coA = co0 + wm * 64 + mi * 16 + gid;
        int coB = coA + 8;
        float sA = g_s2[coA], hA = g_h2[coA];
        float sB = g_s2[coB], hB = g_h2[coB];
        #pragma unroll
        for (int ni = 0; ni < 4; ni++) {
            int pg = n0 + wn * 32 + ni * 8 + 2 * tig;
            #pragma unroll
            for (int e = 0; e < 2; e++) {
                int p = pg + e;
                float y = acc[mi][ni][e] * sA + hA;
                y = (y > 0.f) ? y : LEAK * y;
                float z = acc[mi][ni][2 + e] * sB + hB;
                z = (z > 0.f) ? z : LEAK * z;
                float y2 = __shfl_down_sync(0xffffffffu, y, 4);
                float z2 = __shfl_down_sync(0xffffffffu, z, 4);
                if (!(gid & 1) && p < NPIX) {
                    g_ps2[(size_t)(coA >> 1) * NPIX + p] = pack2(y, y2);
                    g_ps2[(size_t)(coB >> 1) * NPIX + p] = pack2(z, z2);
                }
            }
        }
    }
}

// ---------------- det head GEMM ----------------------------------------------
__global__ __launch_bounds__(256, 2) void det_mma(float* __restrict__ out)
{
    extern __shared__ unsigned sm[];
    const unsigned smb = (unsigned)__cvta_generic_to_shared(sm);

    const int tid  = threadIdx.x;
    const int lane = tid & 31;
    const int w    = tid >> 5;
    const int gid  = lane >> 2, tig = lane & 3;
    const int wm   = w >> 2,    wn  = w & 3;

    const int m0 = blockIdx.y * 128;
    const int n0 = blockIdx.x * 128;

    const int bpx  = tid >> 1;
    const int kq   = (tid & 1) * 16;
    const int pixg = n0 + bpx;
    const bool px_ok = (pixg < NPIX);
    const unsigned* pb = g_ps2 + (size_t)kq * NPIX + (px_ok ? pixg : 0);

    const int arow  = tid >> 1;
    const int ahalf = tid & 1;
    const unsigned* ap = g_rws + (size_t)(m0 + arow) * 512 + ahalf * 8;
    const int adst = arow * SROW + ahalf * 8;
    const int bdst = (kq ? BH1w : BH0w) + bpx * SROW;

    const unsigned aoff = (unsigned)((wm * 64 + (lane & 15)) * 80 + (lane >> 4) * 16);
    const unsigned boff = (unsigned)((wn * 32 + (lane & 15)) * 80 + (lane >> 4) * 16);

    float acc[4][4][4];
    #pragma unroll
    for (int mi = 0; mi < 4; mi++)
        #pragma unroll
        for (int ni = 0; ni < 4; ni++)
            #pragma unroll
            for (int e = 0; e < 4; e++) acc[mi][ni][e] = 0.f;

    unsigned fv[16];
    auto gatherB = [&](unsigned* dst, int it) {
        const unsigned* p = pb + (size_t)(it * 32) * NPIX;
        #pragma unroll
        for (int i = 0; i < 16; i++)
            dst[i] = px_ok ? p[(size_t)i * NPIX] : 0u;
    };
    auto loadA = [&](unsigned* stage, int it) {
        const unsigned* src = ap + it * 32;
        cp16(stage + AH0w + adst,     src);
        cp16(stage + AH0w + adst + 4, src + 4);
        cp16(stage + AH1w + adst,     src + 16);
        cp16(stage + AH1w + adst + 4, src + 20);
    };

    loadA(sm, 0);
    cp_commit();
    gatherB(fv, 0);

    const int NIT = 512 / 32;   // 16
    int s = 0;
    for (int it = 0; it < NIT; it++) {
        unsigned* base = sm + s * STG;
        {
            uint4* bd = (uint4*)(base + bdst);
            bd[0] = make_uint4(fv[0],  fv[1],  fv[2],  fv[3]);
            bd[1] = make_uint4(fv[4],  fv[5],  fv[6],  fv[7]);
            bd[2] = make_uint4(fv[8],  fv[9],  fv[10], fv[11]);
            bd[3] = make_uint4(fv[12], fv[13], fv[14], fv[15]);
        }
        cp_wait0();
        __syncthreads();

        if (it + 1 < NIT) {
            loadA(sm + (s ^ 1) * STG, it + 1);
            cp_commit();
            gatherB(fv, it + 1);
        }

        mma_tile(smb + (unsigned)s * STGB, aoff, boff, acc);
        s ^= 1;
    }

    #pragma unroll
    for (int mi = 0; mi < 4; mi++) {
        int mA = m0 + wm * 64 + mi * 16 + gid;
        int mB = mA + 8;
        float cA = (mA < KO) ? g_cb[mA] : 0.f;
        float cB2 = (mB < KO) ? g_cb[mB] : 0.f;
        #pragma unroll
        for (int ni = 0; ni < 4; ni++) {
            int pg = n0 + wn * 32 + ni * 8 + 2 * tig;
            #pragma unroll
            for (int e = 0; e < 2; e++) {
                int p = pg + e;
                if (p < NPIX) {
                    int b = p / HW, pp = p - b * HW;
                    if (mA < KO)
                        out[((size_t)b * KO + mA) * HW + pp] = acc[mi][ni][e] + cA;
                    if (mB < KO)
                        out[((size_t)b * KO + mB) * HW + pp] = acc[mi][ni][2 + e] + cB2;
                }
            }
        }
    }
}

// ---------------- launch ----------------------------------------------------
extern "C" void kernel_launch(void* const* d_in, const int* in_sizes, int n_in,
                              void* d_out, int out_size)
{
    const float* feat0 = (const float*)d_in[0];
    const float* feat1 = (const float*)d_in[1];
    const float* w1    = (const float*)d_in[2];
    const float* g1    = (const float*)d_in[3];
    const float* b1    = (const float*)d_in[4];
    const float* m1    = (const float*)d_in[5];
    const float* v1    = (const float*)d_in[6];
    const float* w2    = (const float*)d_in[7];
    const float* g2    = (const float*)d_in[8];
    const float* b2    = (const float*)d_in[9];
    const float* m2    = (const float*)d_in[10];
    const float* v2    = (const float*)d_in[11];
    const float* rw    = (const float*)d_in[12];
    float* out = (float*)d_out;

    cudaFuncSetAttribute(conv1_mma, cudaFuncAttributeMaxDynamicSharedMemorySize, SMEMB);
    cudaFuncSetAttribute(conv2_mma, cudaFuncAttributeMaxDynamicSharedMemorySize, SMEMB);
    cudaFuncSetAttribute(det_mma,   cudaFuncAttributeMaxDynamicSharedMemorySize, SMEMB);

    prep_kernel<<<1280, 256>>>(w1, g1, b1, m1, v1, g2, b2, m2, v2, rw);
    prep_w2<<<1024, 256>>>(w2);
    feat0_split<<<46208, 256>>>(feat0);
    feat1_split<<<92416, 256>>>(feat1);
    conv1_mma<<<722, 256, SMEMB>>>();              // N-tiles = 92416/128
    conv2_mma<<<dim3(181, 8), 256, SMEMB>>>();
    det_mma  <<<dim3(181, 5), 256, SMEMB>>>(out);
}

// round 15
// speedup vs baseline: 1.3888x; 1.0253x over previous
#include <cuda_runtime.h>
#include <cuda_fp16.h>

#define LEAK  0.1f
#define BNEPS 1e-5f

#define NB    64
#define HW    361            // 19*19
#define H19   19
#define C2IN  1280
#define C2K   11520          // 1280*9 (fp16 K total)
#define KWORD 5760           // C2K/2 u32 words per weight row
#define KO    600
#define KOP   640
#define NPIX  (NB * HW)      // 23104
#define NPIXF (NB * 1444)    // 92416 (feat1 pixels), divisible by 128

#define SROW  20             // smem row stride in u32 (80 B)
#define AH0w  0
#define AH1w  2560
#define BH0w  5120
#define BH1w  7680
#define STG   10240          // u32 per stage
#define STGB  40960u
#define SMEMB (2 * STG * 4)  // 81920 bytes

// ---------------- device scratch ----------------
__device__ float g_s1[64],  g_h1[64];
__device__ float g_s2[1024], g_h2[1024];
__device__ float g_cb[KO];
__device__ unsigned g_xh2[(size_t)(C2IN / 2) * NPIX];   // conv2 input, ch-paired fp16
__device__ unsigned g_ps2[(size_t)512 * NPIX];          // det input, ch-paired fp16
__device__ __align__(16) unsigned g_w2s[(size_t)1024 * KWORD]; // w2 pairs, K-order r*1280+c
__device__ __align__(16) unsigned g_rws[(size_t)KOP * 512];
__device__ __align__(16) unsigned g_w1s[(size_t)128 * 256];    // w1 pairs (rows 64..127 zero)

__device__ __forceinline__ unsigned pack2(float lo, float hi)
{
    __half2 h = __floats2half2_rn(lo, hi);
    return *reinterpret_cast<unsigned*>(&h);
}

// ---------------- cp.async helpers ----------------
__device__ __forceinline__ void cp16(void* smem, const void* g)
{
    unsigned sa = (unsigned)__cvta_generic_to_shared(smem);
    asm volatile("cp.async.cg.shared.global [%0], [%1], 16;\n" :: "r"(sa), "l"(g));
}
__device__ __forceinline__ void cp_commit() { asm volatile("cp.async.commit_group;\n"); }
__device__ __forceinline__ void cp_wait0()  { asm volatile("cp.async.wait_group 0;\n"); }

// ---------------- prep (small tensors) ----------------
__global__ void prep_kernel(const float* __restrict__ w1,
                            const float* __restrict__ g1, const float* __restrict__ b1,
                            const float* __restrict__ m1, const float* __restrict__ v1,
                            const float* __restrict__ g2, const float* __restrict__ b2,
                            const float* __restrict__ m2, const float* __restrict__ v2,
                            const float* __restrict__ rw)
{
    int i = blockIdx.x * blockDim.x + threadIdx.x;
    if (i < KOP * 512) {
        int m = i >> 9, j = i & 511;
        float x0 = (m < KO) ? rw[m * 1025 + 2 * j]     : 0.f;
        float x1 = (m < KO) ? rw[m * 1025 + 2 * j + 1] : 0.f;
        g_rws[i] = pack2(x0, x1);
    }
    if (i < 128 * 256) {
        int co = i >> 8, j = i & 255;
        float x0 = (co < 64) ? w1[co * 512 + 2 * j]     : 0.f;
        float x1 = (co < 64) ? w1[co * 512 + 2 * j + 1] : 0.f;
        g_w1s[i] = pack2(x0, x1);
    }
    if (i < KO)   g_cb[i] = rw[i * 1025 + 1024];
    if (i < 64)   { float s = g1[i] * rsqrtf(v1[i] + BNEPS); g_s1[i] = s; g_h1[i] = b1[i] - m1[i] * s; }
    if (i < 1024) { float s = g2[i] * rsqrtf(v2[i] + BNEPS); g_s2[i] = s; g_h2[i] = b2[i] - m2[i] * s; }
}

// ---------------- prep w2: coalesced transpose via smem row stage -----------
__global__ __launch_bounds__(512) void prep_w2(const float* __restrict__ w2)
{
    __shared__ float row[C2K];
    const int co = blockIdx.x;
    const float* src = w2 + (size_t)co * C2K;
    for (int i = threadIdx.x; i < C2K; i += 512) row[i] = src[i];
    __syncthreads();
    unsigned* dst = g_w2s + (size_t)co * KWORD;
    for (int j = threadIdx.x; j < KWORD; j += 512) {
        int r = j / 640;
        int c = (j - r * 640) * 2;
        dst[j] = pack2(row[c * 9 + r], row[c * 9 + 9 + r]);
    }
}

// ---------------- feat0 -> g_xh2 channel-pairs 128..639 ----------------
__global__ void feat0_split(const float* __restrict__ feat0)
{
    long long i = (long long)blockIdx.x * blockDim.x + threadIdx.x;
    if (i < (long long)NB * 512 * HW) {
        int hw = (int)(i % HW);
        long long t = i / HW;
        int cp = (int)(t & 511);
        int b  = (int)(t >> 9);
        const float* src = feat0 + ((size_t)b * 1024 + 2 * cp) * HW + hw;
        g_xh2[(size_t)(128 + cp) * NPIX + b * HW + hw] = pack2(src[0], src[HW]);
    }
}

// ---------------- mma / ldmatrix helpers ----------------
__device__ __forceinline__ void mma16816(float* d, const unsigned* a, const unsigned* b)
{
    asm volatile(
        "mma.sync.aligned.m16n8k16.row.col.f32.f16.f16.f32 "
        "{%0,%1,%2,%3},{%4,%5,%6,%7},{%8,%9},{%0,%1,%2,%3};"
        : "+f"(d[0]), "+f"(d[1]), "+f"(d[2]), "+f"(d[3])
        : "r"(a[0]), "r"(a[1]), "r"(a[2]), "r"(a[3]), "r"(b[0]), "r"(b[1]));
}

__device__ __forceinline__ void ldsm4(unsigned& r0, unsigned& r1, unsigned& r2, unsigned& r3,
                                      unsigned saddr)
{
    asm volatile("ldmatrix.sync.aligned.m8n8.x4.shared.b16 {%0,%1,%2,%3}, [%4];"
                 : "=r"(r0), "=r"(r1), "=r"(r2), "=r"(r3) : "r"(saddr));
}

// 64x32 warp tile, K=64/stage, software-pipelined fragments
__device__ __forceinline__ void mma_tile(unsigned sb, unsigned aoff, unsigned boff,
                                         float acc[4][4][4])
{
    const unsigned ABASE[4] = { sb + aoff,            sb + aoff + 32u,
                                sb + 10240u + aoff,   sb + 10240u + aoff + 32u };
    const unsigned BBASE[4] = { sb + 20480u + boff,   sb + 20480u + boff + 32u,
                                sb + 30720u + boff,   sb + 30720u + boff + 32u };

    unsigned bfr[2][4][2];
    unsigned afr[2][4];

    ldsm4(bfr[0][0][0], bfr[0][1][0], bfr[0][0][1], bfr[0][1][1], BBASE[0]);
    ldsm4(bfr[0][2][0], bfr[0][3][0], bfr[0][2][1], bfr[0][3][1], BBASE[0] + 1280u);
    ldsm4(afr[0][0], afr[0][1], afr[0][2], afr[0][3], ABASE[0]);

    #pragma unroll
    for (int g = 0; g < 4; g++) {
        const int bc = g & 1;
        #pragma unroll
        for (int mi = 0; mi < 4; mi++) {
            const int ac = mi & 1;
            if (mi < 3) {
                ldsm4(afr[ac ^ 1][0], afr[ac ^ 1][1], afr[ac ^ 1][2], afr[ac ^ 1][3],
                      ABASE[g] + (mi + 1) * 1280u);
            } else if (g < 3) {
                ldsm4(bfr[bc ^ 1][0][0], bfr[bc ^ 1][1][0], bfr[bc ^ 1][0][1], bfr[bc ^ 1][1][1],
                      BBASE[g + 1]);
                ldsm4(bfr[bc ^ 1][2][0], bfr[bc ^ 1][3][0], bfr[bc ^ 1][2][1], bfr[bc ^ 1][3][1],
                      BBASE[g + 1] + 1280u);
                ldsm4(afr[ac ^ 1][0], afr[ac ^ 1][1], afr[ac ^ 1][2], afr[ac ^ 1][3],
                      ABASE[g + 1]);
            }
            #pragma unroll
            for (int ni = 0; ni < 4; ni++)
                mma16816(acc[mi][ni], afr[ac], bfr[bc][ni]);
        }
    }
}

// ---------------- conv1 GEMM: fused fp32 gather, M=64(pad128) x K=512 -------
__global__ __launch_bounds__(256, 2) void conv1_mma(const float* __restrict__ feat1)
{
    extern __shared__ unsigned sm[];
    const unsigned smb = (unsigned)__cvta_generic_to_shared(sm);

    const int tid  = threadIdx.x;
    const int lane = tid & 31;
    const int w    = tid >> 5;
    const int gid  = lane >> 2, tig = lane & 3;
    const int wm   = w >> 2,    wn  = w & 3;

    const int n0 = blockIdx.x * 128;

    const int bpx  = tid >> 1;
    const int kq   = (tid & 1) * 16;            // word offset in iter's 32 words
    const int pixg = n0 + bpx;                  // always < NPIXF
    const int bimg = pixg / 1444;
    const int hw   = pixg - bimg * 1444;
    // base: channel (2*kq) of image bimg at pixel hw; channel stride 1444 floats
    const float* fb = feat1 + ((size_t)bimg * 512 + 2 * kq) * 1444 + hw;

    const int arow  = tid >> 1;
    const int ahalf = tid & 1;
    const unsigned* ap = g_w1s + (size_t)arow * 256 + ahalf * 8;
    const int adst = arow * SROW + ahalf * 8;
    const int bdst = (kq ? BH1w : BH0w) + bpx * SROW;

    const unsigned aoff = (unsigned)((wm * 64 + (lane & 15)) * 80 + (lane >> 4) * 16);
    const unsigned boff = (unsigned)((wn * 32 + (lane & 15)) * 80 + (lane >> 4) * 16);

    float acc[4][4][4];
    #pragma unroll
    for (int mi = 0; mi < 4; mi++)
        #pragma unroll
        for (int ni = 0; ni < 4; ni++)
            #pragma unroll
            for (int e = 0; e < 4; e++) acc[mi][ni][e] = 0.f;

    unsigned fv[16];
    auto gatherB = [&](unsigned* dst, int it) {
        // iter it covers fp16 channels [it*64, it*64+64); this thread: 32 of them
        const float* p = fb + (size_t)(it * 64) * 1444;
        #pragma unroll
        for (int i = 0; i < 16; i++) {
            float x0 = p[(size_t)(2 * i)     * 1444];
            float x1 = p[(size_t)(2 * i + 1) * 1444];
            dst[i] = pack2(x0, x1);
        }
    };
    auto loadA = [&](unsigned* stage, int it) {
        const unsigned* src = ap + it * 32;
        cp16(stage + AH0w + adst,     src);
        cp16(stage + AH0w + adst + 4, src + 4);
        cp16(stage + AH1w + adst,     src + 16);
        cp16(stage + AH1w + adst + 4, src + 20);
    };

    loadA(sm, 0);
    cp_commit();
    gatherB(fv, 0);

    const int NIT = 256 / 32;   // 8
    int s = 0;
    for (int it = 0; it < NIT; it++) {
        unsigned* base = sm + s * STG;
        {
            uint4* bd = (uint4*)(base + bdst);
            bd[0] = make_uint4(fv[0],  fv[1],  fv[2],  fv[3]);
            bd[1] = make_uint4(fv[4],  fv[5],  fv[6],  fv[7]);
            bd[2] = make_uint4(fv[8],  fv[9],  fv[10], fv[11]);
            bd[3] = make_uint4(fv[12], fv[13], fv[14], fv[15]);
        }
        cp_wait0();
        __syncthreads();

        if (it + 1 < NIT) {
            loadA(sm + (s ^ 1) * STG, it + 1);
            cp_commit();
            gatherB(fv, it + 1);
        }

        mma_tile(smb + (unsigned)s * STGB, aoff, boff, acc);
        s ^= 1;
    }

    // epilogue: only wm==0 rows (co 0..63) valid; BN + leaky + reorg scatter
    if (wm == 0) {
        #pragma unroll
        for (int mi = 0; mi < 4; mi++) {
            int coA = mi * 16 + gid;
            int coB = coA + 8;
            float sA = g_s1[coA], hA = g_h1[coA];
            float sB = g_s1[coB], hB = g_h1[coB];
            #pragma unroll
            for (int ni = 0; ni < 4; ni++) {
                int pg = n0 + wn * 32 + ni * 8 + 2 * tig;
                #pragma unroll
                for (int e = 0; e < 2; e++) {
                    int p = pg + e;
                    float y = acc[mi][ni][e] * sA + hA;
                    y = (y > 0.f) ? y : LEAK * y;
                    float z = acc[mi][ni][2 + e] * sB + hB;
                    z = (z > 0.f) ? z : LEAK * z;
                    float y2 = __shfl_down_sync(0xffffffffu, y, 4);
                    float z2 = __shfl_down_sync(0xffffffffu, z, 4);
                    if (!(gid & 1)) {
                        int b   = p / 1444, pix = p - b * 1444;
                        int h38 = pix / 38,  w38 = pix - h38 * 38;
                        int quad = (h38 & 1) * 2 + (w38 & 1);
                        int gp  = b * HW + (h38 >> 1) * H19 + (w38 >> 1);
                        int ccA = quad * 64 + coA;
                        int ccB = quad * 64 + coB;
                        g_xh2[(size_t)(ccA >> 1) * NPIX + gp] = pack2(y, y2);
                        g_xh2[(size_t)(ccB >> 1) * NPIX + gp] = pack2(z, z2);
                    }
                }
            }
        }
    }
}

// ---------------- conv2 (plain fp16, 256 thr, 8 warps 64x32, pipelined) -----
__global__ __launch_bounds__(256, 2) void conv2_mma()
{
    extern __shared__ unsigned sm[];
    const unsigned smb = (unsigned)__cvta_generic_to_shared(sm);

    const int tid  = threadIdx.x;
    const int lane = tid & 31;
    const int w    = tid >> 5;
    const int gid  = lane >> 2, tig = lane & 3;
    const int wm   = w >> 2,    wn  = w & 3;

    const int co0 = blockIdx.y * 128;
    const int n0  = blockIdx.x * 128;

    const int bpx  = tid >> 1;
    const int kq   = (tid & 1) * 16;
    const int pixg = n0 + bpx;
    const bool px_ok = (pixg < NPIX);
    int sp_base = 0;
    unsigned vmask = 0;
    if (px_ok) {
        int bimg = pixg / HW;
        int pix  = pixg - bimg * HW;
        int oh = pix / H19, ow = pix - oh * H19;
        sp_base = bimg * HW + pix;
        #pragma unroll
        for (int r = 0; r < 9; r++) {
            int ih = oh + r / 3 - 1, iw = ow + r % 3 - 1;
            if ((unsigned)ih < 19u && (unsigned)iw < 19u) vmask |= 1u << r;
        }
    }
    int wb = kq, rB = 0;

    const int arow  = tid >> 1;
    const int ahalf = tid & 1;
    const unsigned* ap = g_w2s + (size_t)(co0 + arow) * KWORD + ahalf * 8;
    const int adst = arow * SROW + ahalf * 8;
    const int bdst = (kq ? BH1w : BH0w) + bpx * SROW;

    const unsigned aoff = (unsigned)((wm * 64 + (lane & 15)) * 80 + (lane >> 4) * 16);
    const unsigned boff = (unsigned)((wn * 32 + (lane & 15)) * 80 + (lane >> 4) * 16);

    float acc[4][4][4];
    #pragma unroll
    for (int mi = 0; mi < 4; mi++)
        #pragma unroll
        for (int ni = 0; ni < 4; ni++)
            #pragma unroll
            for (int e = 0; e < 4; e++) acc[mi][ni][e] = 0.f;

    unsigned fv[16];
    auto gatherB = [&](unsigned* dst) {
        bool val = px_ok && ((vmask >> rB) & 1u);
        int dy  = (rB * 11) >> 5;
        int off = dy * H19 + (rB - dy * 3) - 20;
        const unsigned* p = g_xh2 + (size_t)wb * NPIX + (sp_base + off);
        #pragma unroll
        for (int i = 0; i < 16; i++)
            dst[i] = val ? p[(size_t)i * NPIX] : 0u;
        wb += 32;
        if (wb >= 640) { wb -= 640; ++rB; }
    };
    auto loadA = [&](unsigned* stage, int it) {
        const unsigned* src = ap + it * 32;
        cp16(stage + AH0w + adst,     src);
        cp16(stage + AH0w + adst + 4, src + 4);
        cp16(stage + AH1w + adst,     src + 16);
        cp16(stage + AH1w + adst + 4, src + 20);
    };

    loadA(sm, 0);
    cp_commit();
    gatherB(fv);

    const int NIT = KWORD / 32;   // 180
    int s = 0;
    for (int it = 0; it < NIT; it++) {
        unsigned* base = sm + s * STG;
        {
            uint4* bd = (uint4*)(base + bdst);
            bd[0] = make_uint4(fv[0],  fv[1],  fv[2],  fv[3]);
            bd[1] = make_uint4(fv[4],  fv[5],  fv[6],  fv[7]);
            bd[2] = make_uint4(fv[8],  fv[9],  fv[10], fv[11]);
            bd[3] = make_uint4(fv[12], fv[13], fv[14], fv[15]);
        }
        cp_wait0();
        __syncthreads();

        if (it + 1 < NIT) {
            loadA(sm + (s ^ 1) * STG, it + 1);
            cp_commit();
            gatherB(fv);
        }

        mma_tile(smb + (unsigned)s * STGB, aoff, boff, acc);
        s ^= 1;
    }

    #pragma unroll
    for (int mi = 0; mi < 4; mi++) {
        int coA = co0 + wm * 64 + mi * 16 + gid;
        int coB = coA + 8;
        float sA = g_s2[coA], hA = g_h2[coA];
        float sB = g_s2[coB], hB = g_h2[coB];
        #pragma unroll
        for (int ni = 0; ni < 4; ni++) {
            int pg = n0 + wn * 32 + ni * 8 + 2 * tig;
            #pragma unroll
            for (int e = 0; e < 2; e++) {
                int p = pg + e;
                float y = acc[mi][ni][e] * sA + hA;
                y = (y > 0.f) ? y : LEAK * y;
                float z = acc[mi][ni][2 + e] * sB + hB;
                z = (z > 0.f) ? z : LEAK * z;
                float y2 = __shfl_down_sync(0xffffffffu, y, 4);
                float z2 = __shfl_down_sync(0xffffffffu, z, 4);
                if (!(gid & 1) && p < NPIX) {
                    g_ps2[(size_t)(coA >> 1) * NPIX + p] = pack2(y, y2);
                    g_ps2[(size_t)(coB >> 1) * NPIX + p] = pack2(z, z2);
                }
            }
        }
    }
}

// ---------------- det head GEMM ----------------------------------------------
__global__ __launch_bounds__(256, 2) void det_mma(float* __restrict__ out)
{
    extern __shared__ unsigned sm[];
    const unsigned smb = (unsigned)__cvta_generic_to_shared(sm);

    const int tid  = threadIdx.x;
    const int lane = tid & 31;
    const int w    = tid >> 5;
    const int gid  = lane >> 2, tig = lane & 3;
    const int wm   = w >> 2,    wn  = w & 3;

    const int m0 = blockIdx.y * 128;
    const int n0 = blockIdx.x * 128;

    const int bpx  = tid >> 1;
    const int kq   = (tid & 1) * 16;
    const int pixg = n0 + bpx;
    const bool px_ok = (pixg < NPIX);
    const unsigned* pb = g_ps2 + (size_t)kq * NPIX + (px_ok ? pixg : 0);

    const int arow  = tid >> 1;
    const int ahalf = tid & 1;
    const unsigned* ap = g_rws + (size_t)(m0 + arow) * 512 + ahalf * 8;
    const int adst = arow * SROW + ahalf * 8;
    const int bdst = (kq ? BH1w : BH0w) + bpx * SROW;

    const unsigned aoff = (unsigned)((wm * 64 + (lane & 15)) * 80 + (lane >> 4) * 16);
    const unsigned boff = (unsigned)((wn * 32 + (lane & 15)) * 80 + (lane >> 4) * 16);

    float acc[4][4][4];
    #pragma unroll
    for (int mi = 0; mi < 4; mi++)
        #pragma unroll
        for (int ni = 0; ni < 4; ni++)
            #pragma unroll
            for (int e = 0; e < 4; e++) acc[mi][ni][e] = 0.f;

    unsigned fv[16];
    auto gatherB = [&](unsigned* dst, int it) {
        const unsigned* p = pb + (size_t)(it * 32) * NPIX;
        #pragma unroll
        for (int i = 0; i < 16; i++)
            dst[i] = px_ok ? p[(size_t)i * NPIX] : 0u;
    };
    auto loadA = [&](unsigned* stage, int it) {
        const unsigned* src = ap + it * 32;
        cp16(stage + AH0w + adst,     src);
        cp16(stage + AH0w + adst + 4, src + 4);
        cp16(stage + AH1w + adst,     src + 16);
        cp16(stage + AH1w + adst + 4, src + 20);
    };

    loadA(sm, 0);
    cp_commit();
    gatherB(fv, 0);

    const int NIT = 512 / 32;   // 16
    int s = 0;
    for (int it = 0; it < NIT; it++) {
        unsigned* base = sm + s * STG;
        {
            uint4* bd = (uint4*)(base + bdst);
            bd[0] = make_uint4(fv[0],  fv[1],  fv[2],  fv[3]);
            bd[1] = make_uint4(fv[4],  fv[5],  fv[6],  fv[7]);
            bd[2] = make_uint4(fv[8],  fv[9],  fv[10], fv[11]);
            bd[3] = make_uint4(fv[12], fv[13], fv[14], fv[15]);
        }
        cp_wait0();
        __syncthreads();

        if (it + 1 < NIT) {
            loadA(sm + (s ^ 1) * STG, it + 1);
            cp_commit();
            gatherB(fv, it + 1);
        }

        mma_tile(smb + (unsigned)s * STGB, aoff, boff, acc);
        s ^= 1;
    }

    #pragma unroll
    for (int mi = 0; mi < 4; mi++) {
        int mA = m0 + wm * 64 + mi * 16 + gid;
        int mB = mA + 8;
        float cA = (mA < KO) ? g_cb[mA] : 0.f;
        float cB2 = (mB < KO) ? g_cb[mB] : 0.f;
        #pragma unroll
        for (int ni = 0; ni < 4; ni++) {
            int pg = n0 + wn * 32 + ni * 8 + 2 * tig;
            #pragma unroll
            for (int e = 0; e < 2; e++) {
                int p = pg + e;
                if (p < NPIX) {
                    int b = p / HW, pp = p - b * HW;
                    if (mA < KO)
                        out[((size_t)b * KO + mA) * HW + pp] = acc[mi][ni][e] + cA;
                    if (mB < KO)
                        out[((size_t)b * KO + mB) * HW + pp] = acc[mi][ni][2 + e] + cB2;
                }
            }
        }
    }
}

// ---------------- launch ----------------------------------------------------
extern "C" void kernel_launch(void* const* d_in, const int* in_sizes, int n_in,
                              void* d_out, int out_size)
{
    const float* feat0 = (const float*)d_in[0];
    const float* feat1 = (const float*)d_in[1];
    const float* w1    = (const float*)d_in[2];
    const float* g1    = (const float*)d_in[3];
    const float* b1    = (const float*)d_in[4];
    const float* m1    = (const float*)d_in[5];
    const float* v1    = (const float*)d_in[6];
    const float* w2    = (const float*)d_in[7];
    const float* g2    = (const float*)d_in[8];
    const float* b2    = (const float*)d_in[9];
    const float* m2    = (const float*)d_in[10];
    const float* v2    = (const float*)d_in[11];
    const float* rw    = (const float*)d_in[12];
    float* out = (float*)d_out;

    cudaFuncSetAttribute(conv1_mma, cudaFuncAttributeMaxDynamicSharedMemorySize, SMEMB);
    cudaFuncSetAttribute(conv2_mma, cudaFuncAttributeMaxDynamicSharedMemorySize, SMEMB);
    cudaFuncSetAttribute(det_mma,   cudaFuncAttributeMaxDynamicSharedMemorySize, SMEMB);

    prep_kernel<<<1280, 256>>>(w1, g1, b1, m1, v1, g2, b2, m2, v2, rw);
    prep_w2<<<1024, 512>>>(w2);
    feat0_split<<<46208, 256>>>(feat0);
    conv1_mma<<<722, 256, SMEMB>>>(feat1);         // N-tiles = 92416/128
    conv2_mma<<<dim3(181, 8), 256, SMEMB>>>();
    det_mma  <<<dim3(181, 5), 256, SMEMB>>>(out);
}

// round 16
// speedup vs baseline: 1.3913x; 1.0018x over previous
#include <cuda_runtime.h>
#include <cuda_fp16.h>

#define LEAK  0.1f
#define BNEPS 1e-5f

#define NB    64
#define HW    361            // 19*19
#define H19   19
#define C2IN  1280
#define C2K   11520          // 1280*9 (fp16 K total)
#define KWORD 5760           // C2K/2 u32 words per weight row
#define KO    600
#define KOP   640
#define NPIX  (NB * HW)      // 23104
#define NPIXF (NB * 1444)    // 92416 (feat1 pixels), divisible by 128

#define SROW  20             // smem row stride in u32 (80 B)
#define AH0w  0
#define AH1w  2560
#define BH0w  5120
#define BH1w  7680
#define STG   10240          // u32 per stage
#define STGB  40960u
#define SMEMB (2 * STG * 4)  // 81920 bytes

// ---------------- device scratch ----------------
__device__ float g_s1[64],  g_h1[64];
__device__ float g_s2[1024], g_h2[1024];
__device__ float g_cb[KO];
__device__ unsigned g_xh2[(size_t)(C2IN / 2) * NPIX];   // conv2 input, ch-paired fp16
__device__ unsigned g_ps2[(size_t)512 * NPIX];          // det input, ch-paired fp16
__device__ __align__(16) unsigned g_w2s[(size_t)1024 * KWORD]; // w2 pairs, K-order r*1280+c
__device__ __align__(16) unsigned g_rws[(size_t)KOP * 512];
__device__ __align__(16) unsigned g_w1s[(size_t)128 * 256];    // w1 pairs (rows 64..127 zero)

__device__ __forceinline__ unsigned pack2(float lo, float hi)
{
    __half2 h = __floats2half2_rn(lo, hi);
    return *reinterpret_cast<unsigned*>(&h);
}

// ---------------- cp.async helpers ----------------
__device__ __forceinline__ void cp16(void* smem, const void* g)
{
    unsigned sa = (unsigned)__cvta_generic_to_shared(smem);
    asm volatile("cp.async.cg.shared.global [%0], [%1], 16;\n" :: "r"(sa), "l"(g));
}
__device__ __forceinline__ void cp_commit() { asm volatile("cp.async.commit_group;\n"); }
__device__ __forceinline__ void cp_wait0()  { asm volatile("cp.async.wait_group 0;\n"); }

// ---------------- prep (small tensors) ----------------
__global__ void prep_kernel(const float* __restrict__ w1,
                            const float* __restrict__ g1, const float* __restrict__ b1,
                            const float* __restrict__ m1, const float* __restrict__ v1,
                            const float* __restrict__ g2, const float* __restrict__ b2,
                            const float* __restrict__ m2, const float* __restrict__ v2,
                            const float* __restrict__ rw)
{
    int i = blockIdx.x * blockDim.x + threadIdx.x;
    if (i < KOP * 512) {
        int m = i >> 9, j = i & 511;
        float x0 = (m < KO) ? rw[m * 1025 + 2 * j]     : 0.f;
        float x1 = (m < KO) ? rw[m * 1025 + 2 * j + 1] : 0.f;
        g_rws[i] = pack2(x0, x1);
    }
    if (i < 128 * 256) {
        int co = i >> 8, j = i & 255;
        float x0 = (co < 64) ? w1[co * 512 + 2 * j]     : 0.f;
        float x1 = (co < 64) ? w1[co * 512 + 2 * j + 1] : 0.f;
        g_w1s[i] = pack2(x0, x1);
    }
    if (i < KO)   g_cb[i] = rw[i * 1025 + 1024];
    if (i < 64)   { float s = g1[i] * rsqrtf(v1[i] + BNEPS); g_s1[i] = s; g_h1[i] = b1[i] - m1[i] * s; }
    if (i < 1024) { float s = g2[i] * rsqrtf(v2[i] + BNEPS); g_s2[i] = s; g_h2[i] = b2[i] - m2[i] * s; }
}

// ---------------- prep w2: coalesced transpose via smem row stage -----------
__global__ __launch_bounds__(512) void prep_w2(const float* __restrict__ w2)
{
    __shared__ float row[C2K];
    const int co = blockIdx.x;
    const float* src = w2 + (size_t)co * C2K;
    for (int i = threadIdx.x; i < C2K; i += 512) row[i] = src[i];
    __syncthreads();
    unsigned* dst = g_w2s + (size_t)co * KWORD;
    for (int j = threadIdx.x; j < KWORD; j += 512) {
        int r = j / 640;
        int c = (j - r * 640) * 2;
        dst[j] = pack2(row[c * 9 + r], row[c * 9 + 9 + r]);
    }
}

// ---------------- feat0 -> g_xh2 channel-pairs 128..639 (2-px ILP) ----------
__global__ void feat0_split(const float* __restrict__ feat0)
{
    long long i = (long long)blockIdx.x * blockDim.x + threadIdx.x;
    if (i < (long long)NB * 512 * 181) {
        int j  = (int)(i % 181);
        long long t = i / 181;
        int cp = (int)(t & 511);
        int b  = (int)(t >> 9);
        int hw = 2 * j;
        const float* src = feat0 + ((size_t)b * 1024 + 2 * cp) * HW + hw;
        unsigned* dst = g_xh2 + (size_t)(128 + cp) * NPIX + b * HW + hw;
        float a0 = src[0],  a1 = src[HW];
        dst[0] = pack2(a0, a1);
        if (hw + 1 < HW) {
            float b0 = src[1], b1 = src[HW + 1];
            dst[1] = pack2(b0, b1);
        }
    }
}

// ---------------- mma / ldmatrix helpers ----------------
__device__ __forceinline__ void mma16816(float* d, const unsigned* a, const unsigned* b)
{
    asm volatile(
        "mma.sync.aligned.m16n8k16.row.col.f32.f16.f16.f32 "
        "{%0,%1,%2,%3},{%4,%5,%6,%7},{%8,%9},{%0,%1,%2,%3};"
        : "+f"(d[0]), "+f"(d[1]), "+f"(d[2]), "+f"(d[3])
        : "r"(a[0]), "r"(a[1]), "r"(a[2]), "r"(a[3]), "r"(b[0]), "r"(b[1]));
}

__device__ __forceinline__ void ldsm4(unsigned& r0, unsigned& r1, unsigned& r2, unsigned& r3,
                                      unsigned saddr)
{
    asm volatile("ldmatrix.sync.aligned.m8n8.x4.shared.b16 {%0,%1,%2,%3}, [%4];"
                 : "=r"(r0), "=r"(r1), "=r"(r2), "=r"(r3) : "r"(saddr));
}

// 64x32 warp tile, K=64/stage, software-pipelined fragments (conv2/det)
__device__ __forceinline__ void mma_tile(unsigned sb, unsigned aoff, unsigned boff,
                                         float acc[4][4][4])
{
    const unsigned ABASE[4] = { sb + aoff,            sb + aoff + 32u,
                                sb + 10240u + aoff,   sb + 10240u + aoff + 32u };
    const unsigned BBASE[4] = { sb + 20480u + boff,   sb + 20480u + boff + 32u,
                                sb + 30720u + boff,   sb + 30720u + boff + 32u };

    unsigned bfr[2][4][2];
    unsigned afr[2][4];

    ldsm4(bfr[0][0][0], bfr[0][1][0], bfr[0][0][1], bfr[0][1][1], BBASE[0]);
    ldsm4(bfr[0][2][0], bfr[0][3][0], bfr[0][2][1], bfr[0][3][1], BBASE[0] + 1280u);
    ldsm4(afr[0][0], afr[0][1], afr[0][2], afr[0][3], ABASE[0]);

    #pragma unroll
    for (int g = 0; g < 4; g++) {
        const int bc = g & 1;
        #pragma unroll
        for (int mi = 0; mi < 4; mi++) {
            const int ac = mi & 1;
            if (mi < 3) {
                ldsm4(afr[ac ^ 1][0], afr[ac ^ 1][1], afr[ac ^ 1][2], afr[ac ^ 1][3],
                      ABASE[g] + (mi + 1) * 1280u);
            } else if (g < 3) {
                ldsm4(bfr[bc ^ 1][0][0], bfr[bc ^ 1][1][0], bfr[bc ^ 1][0][1], bfr[bc ^ 1][1][1],
                      BBASE[g + 1]);
                ldsm4(bfr[bc ^ 1][2][0], bfr[bc ^ 1][3][0], bfr[bc ^ 1][2][1], bfr[bc ^ 1][3][1],
                      BBASE[g + 1] + 1280u);
                ldsm4(afr[ac ^ 1][0], afr[ac ^ 1][1], afr[ac ^ 1][2], afr[ac ^ 1][3],
                      ABASE[g + 1]);
            }
            #pragma unroll
            for (int ni = 0; ni < 4; ni++)
                mma16816(acc[mi][ni], afr[ac], bfr[bc][ni]);
        }
    }
}

// 32x32 warp tile over K=64 per stage (R12-verified): 32 MMAs, scalar LDS feed
__device__ __forceinline__ void mma_tile32(const unsigned* A0, const unsigned* A1,
                                           const unsigned* B0, const unsigned* B1,
                                           int wm, int wn, int gid, int tig,
                                           float acc[2][4][4])
{
    #pragma unroll
    for (int ch = 0; ch < 2; ch++) {
        const unsigned* Ac = ch ? A1 : A0;
        const unsigned* Bc = ch ? B1 : B0;
        #pragma unroll
        for (int kk = 0; kk < 2; kk++) {
            const int koff = kk * 8;
            unsigned b[4][2];
            #pragma unroll
            for (int ni = 0; ni < 4; ni++) {
                int col = (wn * 32 + ni * 8 + gid) * SROW + koff + tig;
                b[ni][0] = Bc[col]; b[ni][1] = Bc[col + 4];
            }
            #pragma unroll
            for (int mi = 0; mi < 2; mi++) {
                int r0 = (wm * 32 + mi * 16 + gid) * SROW + koff + tig;
                int r1 = r0 + 8 * SROW;
                unsigned a[4] = {Ac[r0], Ac[r1], Ac[r0 + 4], Ac[r1 + 4]};
                #pragma unroll
                for (int ni = 0; ni < 4; ni++)
                    mma16816(acc[mi][ni], a, b[ni]);
            }
        }
    }
}

// ---------------- conv1 GEMM: 512 thr, fused fp32 gather, M=64(pad128) ------
__global__ __launch_bounds__(512, 2) void conv1_mma(const float* __restrict__ feat1)
{
    extern __shared__ unsigned sm[];

    const int tid  = threadIdx.x;
    const int lane = tid & 31;
    const int w    = tid >> 5;            // 0..15
    const int gid  = lane >> 2, tig = lane & 3;
    const int wm   = w >> 2,    wn  = w & 3;   // 4x4 warp grid

    const int n0 = blockIdx.x * 128;

    // B gather: 4 threads/pixel, 8 words (16 fp32 channels) each
    const int bpx = tid >> 2;             // 0..127
    const int bq  = tid & 3;
    const int pixg = n0 + bpx;            // always < NPIXF
    const int bimg = pixg / 1444;
    const int hw   = pixg - bimg * 1444;
    const float* fb = feat1 + ((size_t)bimg * 512 + 16 * bq) * 1444 + hw;

    // A: 4 threads/row, 8 words each
    const int arow = tid >> 2;
    const int aq   = tid & 3;
    const unsigned* ap = g_w1s + (size_t)arow * 256 + aq * 8;
    const int adst = (aq < 2 ? AH0w : AH1w) + arow * SROW + (aq & 1) * 8;
    const int bdst = (bq < 2 ? BH0w : BH1w) + bpx * SROW + (bq & 1) * 8;

    float acc[2][4][4];
    #pragma unroll
    for (int mi = 0; mi < 2; mi++)
        #pragma unroll
        for (int ni = 0; ni < 4; ni++)
            #pragma unroll
            for (int e = 0; e < 4; e++) acc[mi][ni][e] = 0.f;

    unsigned fv[8];
    auto gatherB = [&](unsigned* dst, int it) {
        const float* p = fb + (size_t)(it * 64) * 1444;
        #pragma unroll
        for (int i = 0; i < 8; i++) {
            float x0 = p[(size_t)(2 * i)     * 1444];
            float x1 = p[(size_t)(2 * i + 1) * 1444];
            dst[i] = pack2(x0, x1);
        }
    };
    auto loadA = [&](unsigned* stage, int it) {
        const unsigned* src = ap + it * 32;
        cp16(stage + adst,     src);
        cp16(stage + adst + 4, src + 4);
    };

    loadA(sm, 0);
    cp_commit();
    gatherB(fv, 0);

    const int NIT = 256 / 32;   // 8
    int s = 0;
    for (int it = 0; it < NIT; it++) {
        unsigned* base = sm + s * STG;
        {
            uint4* bd = (uint4*)(base + bdst);
            bd[0] = make_uint4(fv[0], fv[1], fv[2], fv[3]);
            bd[1] = make_uint4(fv[4], fv[5], fv[6], fv[7]);
        }
        cp_wait0();
        __syncthreads();

        if (it + 1 < NIT) {
            loadA(sm + (s ^ 1) * STG, it + 1);
            cp_commit();
            gatherB(fv, it + 1);
        }

        mma_tile32(base + AH0w, base + AH1w, base + BH0w, base + BH1w,
                   wm, wn, gid, tig, acc);
        s ^= 1;
    }

    // epilogue: valid co rows 0..63 -> warp rows wm 0,1; BN + leaky + reorg
    if (wm < 2) {
        #pragma unroll
        for (int mi = 0; mi < 2; mi++) {
            int coA = wm * 32 + mi * 16 + gid;
            int coB = coA + 8;
            float sA = g_s1[coA], hA = g_h1[coA];
            float sB = g_s1[coB], hB = g_h1[coB];
            #pragma unroll
            for (int ni = 0; ni < 4; ni++) {
                int pg = n0 + wn * 32 + ni * 8 + 2 * tig;
                #pragma unroll
                for (int e = 0; e < 2; e++) {
                    int p = pg + e;
                    float y = acc[mi][ni][e] * sA + hA;
                    y = (y > 0.f) ? y : LEAK * y;
                    float z = acc[mi][ni][2 + e] * sB + hB;
                    z = (z > 0.f) ? z : LEAK * z;
                    float y2 = __shfl_down_sync(0xffffffffu, y, 4);
                    float z2 = __shfl_down_sync(0xffffffffu, z, 4);
                    if (!(gid & 1)) {
                        int b   = p / 1444, pix = p - b * 1444;
                        int h38 = pix / 38,  w38 = pix - h38 * 38;
                        int quad = (h38 & 1) * 2 + (w38 & 1);
                        int gp  = b * HW + (h38 >> 1) * H19 + (w38 >> 1);
                        int ccA = quad * 64 + coA;
                        int ccB = quad * 64 + coB;
                        g_xh2[(size_t)(ccA >> 1) * NPIX + gp] = pack2(y, y2);
                        g_xh2[(size_t)(ccB >> 1) * NPIX + gp] = pack2(z, z2);
                    }
                }
            }
        }
    }
}

// ---------------- conv2 (plain fp16, 256 thr, 8 warps 64x32, pipelined) -----
__global__ __launch_bounds__(256, 2) void conv2_mma()
{
    extern __shared__ unsigned sm[];
    const unsigned smb = (unsigned)__cvta_generic_to_shared(sm);

    const int tid  = threadIdx.x;
    const int lane = tid & 31;
    const int w    = tid >> 5;
    const int gid  = lane >> 2, tig = lane & 3;
    const int wm   = w >> 2,    wn  = w & 3;

    const int co0 = blockIdx.y * 128;
    const int n0  = blockIdx.x * 128;

    const int bpx  = tid >> 1;
    const int kq   = (tid & 1) * 16;
    const int pixg = n0 + bpx;
    const bool px_ok = (pixg < NPIX);
    int sp_base = 0;
    unsigned vmask = 0;
    if (px_ok) {
        int bimg = pixg / HW;
        int pix  = pixg - bimg * HW;
        int oh = pix / H19, ow = pix - oh * H19;
        sp_base = bimg * HW + pix;
        #pragma unroll
        for (int r = 0; r < 9; r++) {
            int ih = oh + r / 3 - 1, iw = ow + r % 3 - 1;
            if ((unsigned)ih < 19u && (unsigned)iw < 19u) vmask |= 1u << r;
        }
    }
    int wb = kq, rB = 0;

    const int arow  = tid >> 1;
    const int ahalf = tid & 1;
    const unsigned* ap = g_w2s + (size_t)(co0 + arow) * KWORD + ahalf * 8;
    const int adst = arow * SROW + ahalf * 8;
    const int bdst = (kq ? BH1w : BH0w) + bpx * SROW;

    const unsigned aoff = (unsigned)((wm * 64 + (lane & 15)) * 80 + (lane >> 4) * 16);
    const unsigned boff = (unsigned)((wn * 32 + (lane & 15)) * 80 + (lane >> 4) * 16);

    float acc[4][4][4];
    #pragma unroll
    for (int mi = 0; mi < 4; mi++)
        #pragma unroll
        for (int ni = 0; ni < 4; ni++)
            #pragma unroll
            for (int e = 0; e < 4; e++) acc[mi][ni][e] = 0.f;

    unsigned fv[16];
    auto gatherB = [&](unsigned* dst) {
        bool val = px_ok && ((vmask >> rB) & 1u);
        int dy  = (rB * 11) >> 5;
        int off = dy * H19 + (rB - dy * 3) - 20;
        const unsigned* p = g_xh2 + (size_t)wb * NPIX + (sp_base + off);
        #pragma unroll
        for (int i = 0; i < 16; i++)
            dst[i] = val ? p[(size_t)i * NPIX] : 0u;
        wb += 32;
        if (wb >= 640) { wb -= 640; ++rB; }
    };
    auto loadA = [&](unsigned* stage, int it) {
        const unsigned* src = ap + it * 32;
        cp16(stage + AH0w + adst,     src);
        cp16(stage + AH0w + adst + 4, src + 4);
        cp16(stage + AH1w + adst,     src + 16);
        cp16(stage + AH1w + adst + 4, src + 20);
    };

    loadA(sm, 0);
    cp_commit();
    gatherB(fv);

    const int NIT = KWORD / 32;   // 180
    int s = 0;
    for (int it = 0; it < NIT; it++) {
        unsigned* base = sm + s * STG;
        {
            uint4* bd = (uint4*)(base + bdst);
            bd[0] = make_uint4(fv[0],  fv[1],  fv[2],  fv[3]);
            bd[1] = make_uint4(fv[4],  fv[5],  fv[6],  fv[7]);
            bd[2] = make_uint4(fv[8],  fv[9],  fv[10], fv[11]);
            bd[3] = make_uint4(fv[12], fv[13], fv[14], fv[15]);
        }
        cp_wait0();
        __syncthreads();

        if (it + 1 < NIT) {
            loadA(sm + (s ^ 1) * STG, it + 1);
            cp_commit();
            gatherB(fv);
        }

        mma_tile(smb + (unsigned)s * STGB, aoff, boff, acc);
        s ^= 1;
    }

    #pragma unroll
    for (int mi = 0; mi < 4; mi++) {
        int coA = co0 + wm * 64 + mi * 16 + gid;
        int coB = coA + 8;
        float sA = g_s2[coA], hA = g_h2[coA];
        float sB = g_s2[coB], hB = g_h2[coB];
        #pragma unroll
        for (int ni = 0; ni < 4; ni++) {
            int pg = n0 + wn * 32 + ni * 8 + 2 * tig;
            #pragma unroll
            for (int e = 0; e < 2; e++) {
                int p = pg + e;
                float y = acc[mi][ni][e] * sA + hA;
                y = (y > 0.f) ? y : LEAK * y;
                float z = acc[mi][ni][2 + e] * sB + hB;
                z = (z > 0.f) ? z : LEAK * z;
                float y2 = __shfl_down_sync(0xffffffffu, y, 4);
                float z2 = __shfl_down_sync(0xffffffffu, z, 4);
                if (!(gid & 1) && p < NPIX) {
                    g_ps2[(size_t)(coA >> 1) * NPIX + p] = pack2(y, y2);
                    g_ps2[(size_t)(coB >> 1) * NPIX + p] = pack2(z, z2);
                }
            }
        }
    }
}

// ---------------- det head GEMM ----------------------------------------------
__global__ __launch_bounds__(256, 2) void det_mma(float* __restrict__ out)
{
    extern __shared__ unsigned sm[];
    const unsigned smb = (unsigned)__cvta_generic_to_shared(sm);

    const int tid  = threadIdx.x;
    const int lane = tid & 31;
    const int w    = tid >> 5;
    const int gid  = lane >> 2, tig = lane & 3;
    const int wm   = w >> 2,    wn  = w & 3;

    const int m0 = blockIdx.y * 128;
    const int n0 = blockIdx.x * 128;

    const int bpx  = tid >> 1;
    const int kq   = (tid & 1) * 16;
    const int pixg = n0 + bpx;
    const bool px_ok = (pixg < NPIX);
    const unsigned* pb = g_ps2 + (size_t)kq * NPIX + (px_ok ? pixg : 0);

    const int arow  = tid >> 1;
    const int ahalf = tid & 1;
    const unsigned* ap = g_rws + (size_t)(m0 + arow) * 512 + ahalf * 8;
    const int adst = arow * SROW + ahalf * 8;
    const int bdst = (kq ? BH1w : BH0w) + bpx * SROW;

    const unsigned aoff = (unsigned)((wm * 64 + (lane & 15)) * 80 + (lane >> 4) * 16);
    const unsigned boff = (unsigned)((wn * 32 + (lane & 15)) * 80 + (lane >> 4) * 16);

    float acc[4][4][4];
    #pragma unroll
    for (int mi = 0; mi < 4; mi++)
        #pragma unroll
        for (int ni = 0; ni < 4; ni++)
            #pragma unroll
            for (int e = 0; e < 4; e++) acc[mi][ni][e] = 0.f;

    unsigned fv[16];
    auto gatherB = [&](unsigned* dst, int it) {
        const unsigned* p = pb + (size_t)(it * 32) * NPIX;
        #pragma unroll
        for (int i = 0; i < 16; i++)
            dst[i] = px_ok ? p[(size_t)i * NPIX] : 0u;
    };
    auto loadA = [&](unsigned* stage, int it) {
        const unsigned* src = ap + it * 32;
        cp16(stage + AH0w + adst,     src);
        cp16(stage + AH0w + adst + 4, src + 4);
        cp16(stage + AH1w + adst,     src + 16);
        cp16(stage + AH1w + adst + 4, src + 20);
    };

    loadA(sm, 0);
    cp_commit();
    gatherB(fv, 0);

    const int NIT = 512 / 32;   // 16
    int s = 0;
    for (int it = 0; it < NIT; it++) {
        unsigned* base = sm + s * STG;
        {
            uint4* bd = (uint4*)(base + bdst);
            bd[0] = make_uint4(fv[0],  fv[1],  fv[2],  fv[3]);
            bd[1] = make_uint4(fv[4],  fv[5],  fv[6],  fv[7]);
            bd[2] = make_uint4(fv[8],  fv[9],  fv[10], fv[11]);
            bd[3] = make_uint4(fv[12], fv[13], fv[14], fv[15]);
        }
        cp_wait0();
        __syncthreads();

        if (it + 1 < NIT) {
            loadA(sm + (s ^ 1) * STG, it + 1);
            cp_commit();
            gatherB(fv, it + 1);
        }

        mma_tile(smb + (unsigned)s * STGB, aoff, boff, acc);
        s ^= 1;
    }

    #pragma unroll
    for (int mi = 0; mi < 4; mi++) {
        int mA = m0 + wm * 64 + mi * 16 + gid;
        int mB = mA + 8;
        float cA = (mA < KO) ? g_cb[mA] : 0.f;
        float cB2 = (mB < KO) ? g_cb[mB] : 0.f;
        #pragma unroll
        for (int ni = 0; ni < 4; ni++) {
            int pg = n0 + wn * 32 + ni * 8 + 2 * tig;
            #pragma unroll
            for (int e = 0; e < 2; e++) {
                int p = pg + e;
                if (p < NPIX) {
                    int b = p / HW, pp = p - b * HW;
                    if (mA < KO)
                        out[((size_t)b * KO + mA) * HW + pp] = acc[mi][ni][e] + cA;
                    if (mB < KO)
                        out[((size_t)b * KO + mB) * HW + pp] = acc[mi][ni][2 + e] + cB2;
                }
            }
        }
    }
}

// ---------------- launch ----------------------------------------------------
extern "C" void kernel_launch(void* const* d_in, const int* in_sizes, int n_in,
                              void* d_out, int out_size)
{
    const float* feat0 = (const float*)d_in[0];
    const float* feat1 = (const float*)d_in[1];
    const float* w1    = (const float*)d_in[2];
    const float* g1    = (const float*)d_in[3];
    const float* b1    = (const float*)d_in[4];
    const float* m1    = (const float*)d_in[5];
    const float* v1    = (const float*)d_in[6];
    const float* w2    = (const float*)d_in[7];
    const float* g2    = (const float*)d_in[8];
    const float* b2    = (const float*)d_in[9];
    const float* m2    = (const float*)d_in[10];
    const float* v2    = (const float*)d_in[11];
    const float* rw    = (const float*)d_in[12];
    float* out = (float*)d_out;

    cudaFuncSetAttribute(conv1_mma, cudaFuncAttributeMaxDynamicSharedMemorySize, SMEMB);
    cudaFuncSetAttribute(conv2_mma, cudaFuncAttributeMaxDynamicSharedMemorySize, SMEMB);
    cudaFuncSetAttribute(det_mma,   cudaFuncAttributeMaxDynamicSharedMemorySize, SMEMB);

    prep_kernel<<<1280, 256>>>(w1, g1, b1, m1, v1, g2, b2, m2, v2, rw);
    prep_w2<<<1024, 512>>>(w2);
    feat0_split<<<23168, 256>>>(feat0);
    conv1_mma<<<722, 512, SMEMB>>>(feat1);
    conv2_mma<<<dim3(181, 8), 256, SMEMB>>>();
    det_mma  <<<dim3(181, 5), 256, SMEMB>>>(out);
}